// round 10
// baseline (speedup 1.0000x reference)
#include <cuda_runtime.h>
#include <cstdint>
#include <cstddef>

// ---------------- problem constants ----------------
constexpr int QL     = 1024;
constexpr int BS     = 4;
constexpr int DMODEL = 1024;
constexpr int NHEAD  = 16;
constexpr int NROWS  = QL * BS;           // 4096
constexpr int HCOLS  = 3 * NHEAD * 64;    // 3072
constexpr float SCALE = 0.125f;
constexpr float LNEPS = 1e-5f;

// ---------------- scratch ----------------
__device__ float g_heads[(size_t)NROWS * HCOLS];
__device__ float g_rk[(size_t)QL * DMODEL];
__device__ float g_biask[BS * NHEAD * QL];
__device__ float g_biasr[NHEAD * QL];
__device__ float g_vec[(size_t)NROWS * DMODEL];
__device__ float g_proj[(size_t)NROWS * DMODEL];
__device__ float g_qkvT[(size_t)HCOLS * DMODEL];
__device__ float g_rwT[(size_t)DMODEL * DMODEL];
__device__ float g_owT[(size_t)DMODEL * DMODEL];
__device__ float g_bd[(size_t)64 * 1024 * 1024];   // G[bh][i][m] band scores
__device__ float g_wr[(size_t)NROWS * DMODEL];     // tf32-rounded w
__device__ float g_rr[(size_t)QL * DMODEL];        // tf32-rounded r

__device__ __forceinline__ float tf32r(float x) {
    float y;
    asm("cvt.rna.tf32.f32 %0, %1;" : "=f"(y) : "f"(x));
    return y;
}
__device__ __forceinline__ void mma_tf32(float* d, const uint32_t* a, const uint32_t* b) {
    asm volatile(
        "mma.sync.aligned.m16n8k8.row.col.f32.tf32.tf32.f32 "
        "{%0,%1,%2,%3}, {%4,%5,%6,%7}, {%8,%9}, {%0,%1,%2,%3};\n"
        : "+f"(d[0]), "+f"(d[1]), "+f"(d[2]), "+f"(d[3])
        : "r"(a[0]), "r"(a[1]), "r"(a[2]), "r"(a[3]), "r"(b[0]), "r"(b[1]));
}
__device__ __forceinline__ void cp16(uint32_t saddr, const void* g) {
    asm volatile("cp.async.cg.shared.global [%0], [%1], 16;" :: "r"(saddr), "l"(g));
}
#define CP_COMMIT() asm volatile("cp.async.commit_group;" ::: "memory")
#define CP_WAIT2()  asm volatile("cp.async.wait_group 2;" ::: "memory")
#define CP_WAIT1()  asm volatile("cp.async.wait_group 1;" ::: "memory")
#define CP_WAIT0()  asm volatile("cp.async.wait_group 0;" ::: "memory")

// ---------------- tf32 round-copy ----------------
__global__ __launch_bounds__(256) void round_copy(const float4* __restrict__ in,
                                                  float4* __restrict__ out, int n4) {
    int i = blockIdx.x * 256 + threadIdx.x;
    if (i < n4) {
        float4 v = in[i];
        v.x = tf32r(v.x); v.y = tf32r(v.y); v.z = tf32r(v.z); v.w = tf32r(v.w);
        out[i] = v;
    }
}

// ---------------- weight transpose + tf32 round: out[n][k] = tf32(in[k][n]) ----------------
__global__ __launch_bounds__(256) void transpose_k(const float* __restrict__ in,
                                                   float* __restrict__ out,
                                                   int K, int N) {
    __shared__ float t[32][33];
    int n0 = blockIdx.x * 32, k0 = blockIdx.y * 32;
    int tx = threadIdx.x, ty = threadIdx.y;
    #pragma unroll
    for (int i = 0; i < 32; i += 8)
        t[ty + i][tx] = in[(size_t)(k0 + ty + i) * N + n0 + tx];
    __syncthreads();
    #pragma unroll
    for (int i = 0; i < 32; i += 8)
        out[(size_t)(n0 + ty + i) * K + k0 + tx] = tf32r(t[tx][ty + i]);
}

// ---------------- 3-stage cp.async tf32 GEMM: C = A[M,K] @ BT[N,K]^T ----------------
// Inputs MUST be tf32-pre-rounded. CTA 128x128, 8 warps 2x4, warp 64x32, K-chunk 32.
constexpr int KC = 32;
constexpr int SM_PITCH = 36;
constexpr int GSTG = 128 * SM_PITCH;              // floats per stage per operand
constexpr int NSTG = 3;
constexpr int GEMM_SMEM = NSTG * 2 * GSTG * 4;    // 110592 bytes

__global__ __launch_bounds__(256)
void gemm_tf32(const float* __restrict__ A, const float* __restrict__ BT,
               float* __restrict__ C, int M, int N, int K, int roundOut) {
    extern __shared__ float smx[];
    float* a_s = smx;                     // [NSTG][GSTG]
    float* b_s = smx + NSTG * GSTG;       // [NSTG][GSTG]
    const uint32_t a_sb = (uint32_t)__cvta_generic_to_shared(a_s);
    const uint32_t b_sb = (uint32_t)__cvta_generic_to_shared(b_s);

    const int t = threadIdx.x;
    const int wid = t >> 5, lane = t & 31;
    const int wr = wid >> 2, wc = wid & 3;
    const int qrow = lane >> 2, qcol = lane & 3;
    const int row0 = blockIdx.y * 128, col0 = blockIdx.x * 128;

    const int lr = t >> 3;             // 0..31
    const int kq = (t & 7) * 4;

    float acc[4][4][4] = {};

    auto load_chunk = [&](int c, int s) {
        const int k0 = c * KC;
        #pragma unroll
        for (int i = 0; i < 4; i++) {
            const int r2 = lr + i * 32;
            const uint32_t soff = (uint32_t)(s * GSTG + r2 * SM_PITCH + kq) * 4;
            cp16(a_sb + soff, &A[(size_t)(row0 + r2) * K + k0 + kq]);
            cp16(b_sb + soff, &BT[(size_t)(col0 + r2) * K + k0 + kq]);
        }
        CP_COMMIT();
    };

    const int NC = K / KC;
    #pragma unroll
    for (int p = 0; p < NSTG - 1; p++) load_chunk(p, p);

    for (int c = 0; c < NC; c++) {
        const int s = c % NSTG;
        const int nx = c + NSTG - 1;
        if (nx < NC) load_chunk(nx, nx % NSTG);
        const int ahead = NC - 1 - c;
        if (ahead >= 2)      CP_WAIT2();
        else if (ahead == 1) CP_WAIT1();
        else                 CP_WAIT0();
        __syncthreads();

        const float* av = a_s + s * GSTG;
        const float* bv = b_s + s * GSTG;
        #pragma unroll
        for (int ks = 0; ks < KC / 8; ks++) {
            const int kk = ks * 8;
            uint32_t af[4][4], bf[4][2];
            #pragma unroll
            for (int mt = 0; mt < 4; mt++) {
                const int r0 = wr * 64 + mt * 16 + qrow;
                af[mt][0] = __float_as_uint(av[r0 * SM_PITCH + kk + qcol]);
                af[mt][1] = __float_as_uint(av[(r0 + 8) * SM_PITCH + kk + qcol]);
                af[mt][2] = __float_as_uint(av[r0 * SM_PITCH + kk + qcol + 4]);
                af[mt][3] = __float_as_uint(av[(r0 + 8) * SM_PITCH + kk + qcol + 4]);
            }
            #pragma unroll
            for (int nt = 0; nt < 4; nt++) {
                const int n0 = wc * 32 + nt * 8 + qrow;
                bf[nt][0] = __float_as_uint(bv[n0 * SM_PITCH + kk + qcol]);
                bf[nt][1] = __float_as_uint(bv[n0 * SM_PITCH + kk + qcol + 4]);
            }
            #pragma unroll
            for (int mt = 0; mt < 4; mt++)
                #pragma unroll
                for (int nt = 0; nt < 4; nt++)
                    mma_tf32(acc[mt][nt], af[mt], bf[nt]);
        }
        __syncthreads();
    }

    #pragma unroll
    for (int mt = 0; mt < 4; mt++) {
        const int row = row0 + wr * 64 + mt * 16 + qrow;
        #pragma unroll
        for (int nt = 0; nt < 4; nt++) {
            const int col = col0 + wc * 32 + nt * 8 + qcol * 2;
            float2 v0 = make_float2(acc[mt][nt][0], acc[mt][nt][1]);
            float2 v1 = make_float2(acc[mt][nt][2], acc[mt][nt][3]);
            if (roundOut) {
                v0.x = tf32r(v0.x); v0.y = tf32r(v0.y);
                v1.x = tf32r(v1.x); v1.y = tf32r(v1.y);
            }
            *(float2*)&C[(size_t)row * N + col] = v0;
            *(float2*)&C[(size_t)(row + 8) * N + col] = v1;
        }
    }
}

// ---------------- BD band GEMM: g_bd[bh][i][m] = q_i . rk[m] + biasr[h][m] ----------------
// heads/rk are tf32-pre-rounded. Both K-chunks cp.async'd up-front (2 stages).
constexpr int BD_SMEM = 2 * 2 * GSTG * 4;   // 73728 bytes

__global__ __launch_bounds__(256)
void gemm_bd(const float* __restrict__ heads, const float* __restrict__ rkb,
             const float* __restrict__ brv, float* __restrict__ gbd) {
    const int It = blockIdx.y, Mt = blockIdx.x;
    if (It + Mt < 7) return;
    const int bh = blockIdx.z, b = bh >> 4, h = bh & 15;

    extern __shared__ float smx[];
    float* a_s = smx;                   // [2][GSTG]
    float* b_s = smx + 2 * GSTG;        // [2][GSTG]
    const uint32_t a_sb = (uint32_t)__cvta_generic_to_shared(a_s);
    const uint32_t b_sb = (uint32_t)__cvta_generic_to_shared(b_s);

    const int t = threadIdx.x;
    const int wid = t >> 5, lane = t & 31;
    const int wr = wid >> 2, wc = wid & 3;
    const int qrow = lane >> 2, qcol = lane & 3;
    const int row0 = It * 128, col0 = Mt * 128;

    const int lr = t >> 3;
    const int kq = (t & 7) * 4;

    // issue both chunks
    #pragma unroll
    for (int c = 0; c < 2; c++) {
        const int k0 = c * KC;
        #pragma unroll
        for (int i = 0; i < 4; i++) {
            const int r2 = lr + i * 32;
            const uint32_t soff = (uint32_t)(c * GSTG + r2 * SM_PITCH + kq) * 4;
            cp16(a_sb + soff,
                 &heads[((size_t)(row0 + r2) * BS + b) * HCOLS + h * 64 + k0 + kq]);
            cp16(b_sb + soff,
                 &rkb[(size_t)(col0 + r2) * DMODEL + h * 64 + k0 + kq]);
        }
        CP_COMMIT();
    }

    float acc[4][4][4] = {};

    #pragma unroll
    for (int c = 0; c < 2; c++) {
        if (c == 0) CP_WAIT1(); else CP_WAIT0();
        __syncthreads();
        const float* av = a_s + c * GSTG;
        const float* bv = b_s + c * GSTG;
        #pragma unroll
        for (int ks = 0; ks < KC / 8; ks++) {
            const int kk = ks * 8;
            uint32_t af[4][4], bf[4][2];
            #pragma unroll
            for (int mt = 0; mt < 4; mt++) {
                const int r0 = wr * 64 + mt * 16 + qrow;
                af[mt][0] = __float_as_uint(av[r0 * SM_PITCH + kk + qcol]);
                af[mt][1] = __float_as_uint(av[(r0 + 8) * SM_PITCH + kk + qcol]);
                af[mt][2] = __float_as_uint(av[r0 * SM_PITCH + kk + qcol + 4]);
                af[mt][3] = __float_as_uint(av[(r0 + 8) * SM_PITCH + kk + qcol + 4]);
            }
            #pragma unroll
            for (int nt = 0; nt < 4; nt++) {
                const int n0 = wc * 32 + nt * 8 + qrow;
                bf[nt][0] = __float_as_uint(bv[n0 * SM_PITCH + kk + qcol]);
                bf[nt][1] = __float_as_uint(bv[n0 * SM_PITCH + kk + qcol + 4]);
            }
            #pragma unroll
            for (int mt = 0; mt < 4; mt++)
                #pragma unroll
                for (int nt = 0; nt < 4; nt++)
                    mma_tf32(acc[mt][nt], af[mt], bf[nt]);
        }
    }

    float* gout = gbd + ((size_t)bh << 20);
    const float* br = brv + h * QL;
    #pragma unroll
    for (int mt = 0; mt < 4; mt++) {
        const int row = row0 + wr * 64 + mt * 16 + qrow;
        #pragma unroll
        for (int nt = 0; nt < 4; nt++) {
            const int col = col0 + wc * 32 + nt * 8 + qcol * 2;
            *(float2*)&gout[(size_t)row * 1024 + col] =
                make_float2(acc[mt][nt][0] + br[col], acc[mt][nt][1] + br[col + 1]);
            *(float2*)&gout[(size_t)(row + 8) * 1024 + col] =
                make_float2(acc[mt][nt][2] + br[col], acc[mt][nt][3] + br[col + 1]);
        }
    }
}

// ---------------- bias precompute ----------------
__global__ __launch_bounds__(256) void bias_k_kernel(const float* __restrict__ heads,
                                                     const float* __restrict__ rwb,
                                                     float* __restrict__ bk) {
    int gt = blockIdx.x * 256 + threadIdx.x;
    int wi = gt >> 5, lane = gt & 31;
    int j = wi & (QL - 1);
    int bh = wi >> 10;
    int b = bh >> 4, h = bh & 15;
    const float* kp = heads + ((size_t)j * BS + b) * HCOLS + 1024 + h * 64;
    const float* wp = rwb + h * 64;
    float s = kp[lane] * wp[lane] + kp[lane + 32] * wp[lane + 32];
    #pragma unroll
    for (int o = 16; o; o >>= 1) s += __shfl_xor_sync(0xffffffffu, s, o);
    if (lane == 0) bk[wi] = s;
}
__global__ __launch_bounds__(256) void bias_r_kernel(const float* __restrict__ rk,
                                                     const float* __restrict__ rrb,
                                                     float* __restrict__ brv) {
    int gt = blockIdx.x * 256 + threadIdx.x;
    int wi = gt >> 5, lane = gt & 31;
    int m = wi & (QL - 1);
    int h = wi >> 10;
    const float* rp = rk + (size_t)m * DMODEL + h * 64;
    const float* wp = rrb + h * 64;
    float s = rp[lane] * wp[lane] + rp[lane + 32] * wp[lane + 32];
    #pragma unroll
    for (int o = 16; o; o >>= 1) s += __shfl_xor_sync(0xffffffffu, s, o);
    if (lane == 0) brv[wi] = s;
}

// ---------------- tensor-core flash attention ----------------
// heads tf32-pre-rounded -> pure float4 tile copies, no cvt in loops.
constexpr int QP = 68;
constexpr int VP = 72;
constexpr int ATTN2_FLOATS = 128 * QP + 64 * QP + 64 * VP + 128 * QP + 64;
constexpr int ATTN2_BYTES  = ATTN2_FLOATS * 4;

__global__ __launch_bounds__(256)
void attn2(const float* __restrict__ heads, const float* __restrict__ biask,
           const float* __restrict__ gbd, float* __restrict__ vec) {
    extern __shared__ float sm[];
    float* q_s = sm;
    float* k_s = q_s + 128 * QP;
    float* v_s = k_s + 64 * QP;
    float* p_s = v_s + 64 * VP;
    float* bks = p_s + 128 * QP;

    const int bh = blockIdx.x, b = bh >> 4, h = bh & 15;
    const int ib = (int)gridDim.y - 1 - (int)blockIdx.y;
    const int i0 = ib * 128;
    const int t = threadIdx.x, wid = t >> 5, lane = t & 31;
    const int qr = lane >> 2, qc = lane & 3;
    const int rbase = wid * 16 + qr;

    // Q tile: 128x64, float4 (2048 float4s / 256 threads = 8 each)
    #pragma unroll
    for (int i = 0; i < 8; i++) {
        int e = t + i * 256;
        int ii = e >> 4, d4 = (e & 15) * 4;
        *(float4*)&q_s[ii * QP + d4] =
            *(const float4*)&heads[((size_t)(i0 + ii) * BS + b) * HCOLS + h * 64 + d4];
    }

    float oacc[8][4] = {};
    float m_run[2] = {-1e30f, -1e30f}, l_run[2] = {0.f, 0.f};
    const float* bk = biask + (size_t)(b * NHEAD + h) * QL;
    const size_t gbase = (size_t)bh << 20;

    const int njt = 2 * ib + 2;
    for (int jt = 0; jt < njt; jt++) {
        const int j0 = jt * 64;
        __syncthreads();
        // K/V tiles: 64x64 each, float4 (1024 float4s / 256 = 4 each)
        #pragma unroll
        for (int i = 0; i < 4; i++) {
            int e = t + i * 256;
            int jj = e >> 4, d4 = (e & 15) * 4;
            size_t base = ((size_t)(j0 + jj) * BS + b) * HCOLS + h * 64 + d4;
            *(float4*)&k_s[jj * QP + d4] = *(const float4*)&heads[base + 1024];
            *(float4*)&v_s[jj * VP + d4] = *(const float4*)&heads[base + 2048];
        }
        if (t < 64) bks[t] = bk[j0 + t];
        __syncthreads();

        float sacc[8][4] = {};
        #pragma unroll
        for (int ks = 0; ks < 8; ks++) {
            const int kk = ks * 8;
            uint32_t af[4];
            af[0] = __float_as_uint(q_s[rbase * QP + kk + qc]);
            af[1] = __float_as_uint(q_s[(rbase + 8) * QP + kk + qc]);
            af[2] = __float_as_uint(q_s[rbase * QP + kk + qc + 4]);
            af[3] = __float_as_uint(q_s[(rbase + 8) * QP + kk + qc + 4]);
            #pragma unroll
            for (int nt = 0; nt < 8; nt++) {
                uint32_t bf[2];
                bf[0] = __float_as_uint(k_s[(nt * 8 + qr) * QP + kk + qc]);
                bf[1] = __float_as_uint(k_s[(nt * 8 + qr) * QP + kk + qc + 4]);
                mma_tf32(sacc[nt], af, bf);
            }
        }

        #pragma unroll
        for (int s = 0; s < 2; s++) {
            const int ig = i0 + rbase + s * 8;
            const float* grow = gbd + gbase + (size_t)ig * 1024 + (1023 - ig + j0);
            #pragma unroll
            for (int nt = 0; nt < 8; nt++) {
                #pragma unroll
                for (int r = 0; r < 2; r++) {
                    const int jl = nt * 8 + qc * 2 + r;
                    const int jg = j0 + jl;
                    float v = sacc[nt][s * 2 + r];
                    if (jg <= ig) v = (v + bks[jl] + grow[jl]) * SCALE;
                    else          v = -1e30f;
                    sacc[nt][s * 2 + r] = v;
                }
            }
        }

        #pragma unroll
        for (int s = 0; s < 2; s++) {
            float mx = -1e30f;
            #pragma unroll
            for (int nt = 0; nt < 8; nt++)
                mx = fmaxf(mx, fmaxf(sacc[nt][s * 2], sacc[nt][s * 2 + 1]));
            mx = fmaxf(mx, __shfl_xor_sync(0xffffffffu, mx, 1));
            mx = fmaxf(mx, __shfl_xor_sync(0xffffffffu, mx, 2));
            float mnew = fmaxf(m_run[s], mx);
            float corr = __expf(m_run[s] - mnew);
            float rs = 0.f;
            #pragma unroll
            for (int nt = 0; nt < 8; nt++) {
                float p0 = __expf(sacc[nt][s * 2] - mnew);
                float p1 = __expf(sacc[nt][s * 2 + 1] - mnew);
                sacc[nt][s * 2] = p0; sacc[nt][s * 2 + 1] = p1;
                rs += p0 + p1;
            }
            rs += __shfl_xor_sync(0xffffffffu, rs, 1);
            rs += __shfl_xor_sync(0xffffffffu, rs, 2);
            l_run[s] = l_run[s] * corr + rs;
            m_run[s] = mnew;
            #pragma unroll
            for (int nt = 0; nt < 8; nt++) {
                oacc[nt][s * 2] *= corr;
                oacc[nt][s * 2 + 1] *= corr;
            }
        }

        #pragma unroll
        for (int s = 0; s < 2; s++) {
            #pragma unroll
            for (int nt = 0; nt < 8; nt++) {
                p_s[(rbase + s * 8) * QP + nt * 8 + qc * 2]     = tf32r(sacc[nt][s * 2]);
                p_s[(rbase + s * 8) * QP + nt * 8 + qc * 2 + 1] = tf32r(sacc[nt][s * 2 + 1]);
            }
        }
        __syncwarp();

        #pragma unroll
        for (int ks = 0; ks < 8; ks++) {
            uint32_t af[4];
            af[0] = __float_as_uint(p_s[rbase * QP + ks * 8 + qc]);
            af[1] = __float_as_uint(p_s[(rbase + 8) * QP + ks * 8 + qc]);
            af[2] = __float_as_uint(p_s[rbase * QP + ks * 8 + qc + 4]);
            af[3] = __float_as_uint(p_s[(rbase + 8) * QP + ks * 8 + qc + 4]);
            #pragma unroll
            for (int nt = 0; nt < 8; nt++) {
                uint32_t bf[2];
                bf[0] = __float_as_uint(v_s[(ks * 8 + qc) * VP + nt * 8 + qr]);
                bf[1] = __float_as_uint(v_s[(ks * 8 + qc + 4) * VP + nt * 8 + qr]);
                mma_tf32(oacc[nt], af, bf);
            }
        }
    }

    #pragma unroll
    for (int s = 0; s < 2; s++) {
        const int ig = i0 + rbase + s * 8;
        const float inv = 1.f / l_run[s];
        #pragma unroll
        for (int nt = 0; nt < 8; nt++) {
            float2 o2 = make_float2(tf32r(oacc[nt][s * 2] * inv),
                                    tf32r(oacc[nt][s * 2 + 1] * inv));
            *(float2*)&vec[((size_t)ig * BS + b) * DMODEL + h * 64 + nt * 8 + qc * 2] = o2;
        }
    }
}

// ---------------- residual + layernorm ----------------
__global__ __launch_bounds__(256) void ln_kernel(const float* __restrict__ w,
                                                 const float* __restrict__ proj,
                                                 const float* __restrict__ g,
                                                 const float* __restrict__ bta,
                                                 float* __restrict__ out) {
    __shared__ float red[8];
    const int row = blockIdx.x;
    const int t = threadIdx.x;
    const size_t base = (size_t)row * DMODEL;
    float x[4];
    float s = 0.f;
    #pragma unroll
    for (int u = 0; u < 4; u++) {
        int c = t + u * 256;
        x[u] = w[base + c] + proj[base + c];
        s += x[u];
    }
    #pragma unroll
    for (int o = 16; o; o >>= 1) s += __shfl_xor_sync(0xffffffffu, s, o);
    if ((t & 31) == 0) red[t >> 5] = s;
    __syncthreads();
    float tot = 0.f;
    #pragma unroll
    for (int i = 0; i < 8; i++) tot += red[i];
    const float mu = tot * (1.f / DMODEL);

    float vs = 0.f;
    #pragma unroll
    for (int u = 0; u < 4; u++) { float dd = x[u] - mu; vs += dd * dd; }
    #pragma unroll
    for (int o = 16; o; o >>= 1) vs += __shfl_xor_sync(0xffffffffu, vs, o);
    __syncthreads();
    if ((t & 31) == 0) red[t >> 5] = vs;
    __syncthreads();
    tot = 0.f;
    #pragma unroll
    for (int i = 0; i < 8; i++) tot += red[i];
    const float rstd = rsqrtf(tot * (1.f / DMODEL) + LNEPS);

    #pragma unroll
    for (int u = 0; u < 4; u++) {
        int c = t + u * 256;
        out[base + c] = (x[u] - mu) * rstd * g[c] + bta[c];
    }
}

// ---------------- launch ----------------
extern "C" void kernel_launch(void* const* d_in, const int* in_sizes, int n_in,
                              void* d_out, int out_size) {
    const float* w    = (const float*)d_in[0];
    const float* r    = (const float*)d_in[1];
    const float* qkvw = (const float*)d_in[3];
    const float* rw   = (const float*)d_in[4];
    const float* ow   = (const float*)d_in[5];
    const float* rrb  = (const float*)d_in[6];
    const float* rwb  = (const float*)d_in[7];
    const float* lng  = (const float*)d_in[8];
    const float* lnb  = (const float*)d_in[9];
    float* out = (float*)d_out;

    float *heads, *rkbuf, *bk, *brv, *vec, *proj, *qkvT, *rwT, *owT, *gbd, *wr, *rr;
    cudaGetSymbolAddress((void**)&heads, g_heads);
    cudaGetSymbolAddress((void**)&rkbuf, g_rk);
    cudaGetSymbolAddress((void**)&bk,    g_biask);
    cudaGetSymbolAddress((void**)&brv,   g_biasr);
    cudaGetSymbolAddress((void**)&vec,   g_vec);
    cudaGetSymbolAddress((void**)&proj,  g_proj);
    cudaGetSymbolAddress((void**)&qkvT,  g_qkvT);
    cudaGetSymbolAddress((void**)&rwT,   g_rwT);
    cudaGetSymbolAddress((void**)&owT,   g_owT);
    cudaGetSymbolAddress((void**)&gbd,   g_bd);
    cudaGetSymbolAddress((void**)&wr,    g_wr);
    cudaGetSymbolAddress((void**)&rr,    g_rr);

    cudaFuncSetAttribute(attn2, cudaFuncAttributeMaxDynamicSharedMemorySize, ATTN2_BYTES);
    cudaFuncSetAttribute(gemm_tf32, cudaFuncAttributeMaxDynamicSharedMemorySize, GEMM_SMEM);
    cudaFuncSetAttribute(gemm_bd, cudaFuncAttributeMaxDynamicSharedMemorySize, BD_SMEM);

    // 0) pre-round A operands; transpose + round weights to [N,K]
    round_copy<<<(NROWS * DMODEL / 4) / 256, 256>>>((const float4*)w, (float4*)wr,
                                                    NROWS * DMODEL / 4);
    round_copy<<<(QL * DMODEL / 4) / 256, 256>>>((const float4*)r, (float4*)rr,
                                                 QL * DMODEL / 4);
    transpose_k<<<dim3(HCOLS / 32, DMODEL / 32), dim3(32, 8)>>>(qkvw, qkvT, DMODEL, HCOLS);
    transpose_k<<<dim3(DMODEL / 32, DMODEL / 32), dim3(32, 8)>>>(rw, rwT, DMODEL, DMODEL);
    transpose_k<<<dim3(DMODEL / 32, DMODEL / 32), dim3(32, 8)>>>(ow, owT, DMODEL, DMODEL);

    // 1) heads = w @ qkv_w ; r_k = r @ r_w   (outputs tf32-rounded)
    gemm_tf32<<<dim3(HCOLS / 128, NROWS / 128), 256, GEMM_SMEM>>>(
        wr, qkvT, heads, NROWS, HCOLS, DMODEL, 1);
    gemm_tf32<<<dim3(DMODEL / 128, QL / 128), 256, GEMM_SMEM>>>(
        rr, rwT, rkbuf, QL, DMODEL, DMODEL, 1);
    // 2) biases
    bias_k_kernel<<<(BS * NHEAD * QL * 32) / 256, 256>>>(heads, rwb, bk);
    bias_r_kernel<<<(NHEAD * QL * 32) / 256, 256>>>(rkbuf, rrb, brv);
    // 3) BD band
    gemm_bd<<<dim3(8, 8, 64), 256, BD_SMEM>>>(heads, rkbuf, brv, gbd);
    // 4) tensor-core flash attention (writes tf32-rounded vec)
    attn2<<<dim3(BS * NHEAD, QL / 128), 256, ATTN2_BYTES>>>(heads, bk, gbd, vec);
    // 5) proj = vec @ o_w   (output NOT rounded; feeds LN)
    gemm_tf32<<<dim3(DMODEL / 128, NROWS / 128), 256, GEMM_SMEM>>>(
        vec, owT, proj, NROWS, DMODEL, DMODEL, 0);
    // 6) out = LN(w + proj)
    ln_kernel<<<NROWS, 256>>>(w, proj, lng, lnb, out);
}

// round 11
// speedup vs baseline: 1.5213x; 1.5213x over previous
#include <cuda_runtime.h>
#include <cstdint>
#include <cstddef>

// ---------------- problem constants ----------------
constexpr int QL     = 1024;
constexpr int BS     = 4;
constexpr int DMODEL = 1024;
constexpr int NHEAD  = 16;
constexpr int NROWS  = QL * BS;           // 4096
constexpr int HCOLS  = 3 * NHEAD * 64;    // 3072
constexpr float SCALE = 0.125f;
constexpr float LNEPS = 1e-5f;

// ---------------- scratch ----------------
__device__ float g_heads[(size_t)NROWS * HCOLS];
__device__ float g_rk[(size_t)QL * DMODEL];
__device__ float g_biask[BS * NHEAD * QL];
__device__ float g_biasr[NHEAD * QL];
__device__ float g_vec[(size_t)NROWS * DMODEL];
__device__ float g_proj[(size_t)NROWS * DMODEL];
__device__ float g_qkvT[(size_t)HCOLS * DMODEL];
__device__ float g_rwT[(size_t)DMODEL * DMODEL];
__device__ float g_owT[(size_t)DMODEL * DMODEL];
__device__ float g_bd[(size_t)64 * 1024 * 1024];   // G[bh][i][m] band scores
__device__ float g_wr[(size_t)NROWS * DMODEL];     // tf32-rounded w
__device__ float g_rr[(size_t)QL * DMODEL];        // tf32-rounded r

__device__ __forceinline__ float tf32r(float x) {
    float y;
    asm("cvt.rna.tf32.f32 %0, %1;" : "=f"(y) : "f"(x));
    return y;
}
__device__ __forceinline__ void mma_tf32(float* d, const uint32_t* a, const uint32_t* b) {
    asm volatile(
        "mma.sync.aligned.m16n8k8.row.col.f32.tf32.tf32.f32 "
        "{%0,%1,%2,%3}, {%4,%5,%6,%7}, {%8,%9}, {%0,%1,%2,%3};\n"
        : "+f"(d[0]), "+f"(d[1]), "+f"(d[2]), "+f"(d[3])
        : "r"(a[0]), "r"(a[1]), "r"(a[2]), "r"(a[3]), "r"(b[0]), "r"(b[1]));
}
__device__ __forceinline__ void cp16(uint32_t saddr, const void* g) {
    asm volatile("cp.async.cg.shared.global [%0], [%1], 16;" :: "r"(saddr), "l"(g));
}
#define CP_COMMIT() asm volatile("cp.async.commit_group;" ::: "memory")
#define CP_WAIT1()  asm volatile("cp.async.wait_group 1;" ::: "memory")
#define CP_WAIT0()  asm volatile("cp.async.wait_group 0;" ::: "memory")

// ---------------- tf32 round-copy ----------------
__global__ __launch_bounds__(256) void round_copy(const float4* __restrict__ in,
                                                  float4* __restrict__ out, int n4) {
    int i = blockIdx.x * 256 + threadIdx.x;
    if (i < n4) {
        float4 v = in[i];
        v.x = tf32r(v.x); v.y = tf32r(v.y); v.z = tf32r(v.z); v.w = tf32r(v.w);
        out[i] = v;
    }
}

// ---------------- weight transpose + tf32 round: out[n][k] = tf32(in[k][n]) ----------------
__global__ __launch_bounds__(256) void transpose_k(const float* __restrict__ in,
                                                   float* __restrict__ out,
                                                   int K, int N) {
    __shared__ float t[32][33];
    int n0 = blockIdx.x * 32, k0 = blockIdx.y * 32;
    int tx = threadIdx.x, ty = threadIdx.y;
    #pragma unroll
    for (int i = 0; i < 32; i += 8)
        t[ty + i][tx] = in[(size_t)(k0 + ty + i) * N + n0 + tx];
    __syncthreads();
    #pragma unroll
    for (int i = 0; i < 32; i += 8)
        out[(size_t)(n0 + ty + i) * K + k0 + tx] = tf32r(t[tx][ty + i]);
}

// ---------------- 2-stage cp.async tf32 GEMM: C = A[M,K] @ BT[N,K]^T ----------------
// Inputs MUST be tf32-pre-rounded. CTA 128x128, 8 warps 2x4, warp 64x32, K-chunk 32.
constexpr int KC = 32;
constexpr int SM_PITCH = 36;
constexpr int GSTG = 128 * SM_PITCH;           // floats per stage per operand
constexpr int GEMM_SMEM = 2 * 2 * GSTG * 4;    // 73728 bytes -> 2 CTAs/SM

__global__ __launch_bounds__(256)
void gemm_tf32(const float* __restrict__ A, const float* __restrict__ BT,
               float* __restrict__ C, int M, int N, int K, int roundOut) {
    extern __shared__ float smx[];
    float* a_s = smx;                 // [2][GSTG]
    float* b_s = smx + 2 * GSTG;      // [2][GSTG]
    const uint32_t a_sb = (uint32_t)__cvta_generic_to_shared(a_s);
    const uint32_t b_sb = (uint32_t)__cvta_generic_to_shared(b_s);

    const int t = threadIdx.x;
    const int wid = t >> 5, lane = t & 31;
    const int wr = wid >> 2, wc = wid & 3;
    const int qrow = lane >> 2, qcol = lane & 3;
    const int row0 = blockIdx.y * 128, col0 = blockIdx.x * 128;

    const int lr = t >> 3;             // 0..31
    const int kq = (t & 7) * 4;

    float acc[4][4][4] = {};

    auto load_chunk = [&](int c, int s) {
        const int k0 = c * KC;
        #pragma unroll
        for (int i = 0; i < 4; i++) {
            const int r2 = lr + i * 32;
            const uint32_t soff = (uint32_t)(s * GSTG + r2 * SM_PITCH + kq) * 4;
            cp16(a_sb + soff, &A[(size_t)(row0 + r2) * K + k0 + kq]);
            cp16(b_sb + soff, &BT[(size_t)(col0 + r2) * K + k0 + kq]);
        }
        CP_COMMIT();
    };

    const int NC = K / KC;
    load_chunk(0, 0);

    for (int c = 0; c < NC; c++) {
        const int s = c & 1;
        if (c + 1 < NC) { load_chunk(c + 1, s ^ 1); CP_WAIT1(); }
        else            { CP_WAIT0(); }
        __syncthreads();

        const float* av = a_s + s * GSTG;
        const float* bv = b_s + s * GSTG;
        #pragma unroll
        for (int ks = 0; ks < KC / 8; ks++) {
            const int kk = ks * 8;
            uint32_t af[4][4], bf[4][2];
            #pragma unroll
            for (int mt = 0; mt < 4; mt++) {
                const int r0 = wr * 64 + mt * 16 + qrow;
                af[mt][0] = __float_as_uint(av[r0 * SM_PITCH + kk + qcol]);
                af[mt][1] = __float_as_uint(av[(r0 + 8) * SM_PITCH + kk + qcol]);
                af[mt][2] = __float_as_uint(av[r0 * SM_PITCH + kk + qcol + 4]);
                af[mt][3] = __float_as_uint(av[(r0 + 8) * SM_PITCH + kk + qcol + 4]);
            }
            #pragma unroll
            for (int nt = 0; nt < 4; nt++) {
                const int n0 = wc * 32 + nt * 8 + qrow;
                bf[nt][0] = __float_as_uint(bv[n0 * SM_PITCH + kk + qcol]);
                bf[nt][1] = __float_as_uint(bv[n0 * SM_PITCH + kk + qcol + 4]);
            }
            #pragma unroll
            for (int mt = 0; mt < 4; mt++)
                #pragma unroll
                for (int nt = 0; nt < 4; nt++)
                    mma_tf32(acc[mt][nt], af[mt], bf[nt]);
        }
        __syncthreads();
    }

    #pragma unroll
    for (int mt = 0; mt < 4; mt++) {
        const int row = row0 + wr * 64 + mt * 16 + qrow;
        #pragma unroll
        for (int nt = 0; nt < 4; nt++) {
            const int col = col0 + wc * 32 + nt * 8 + qcol * 2;
            float2 v0 = make_float2(acc[mt][nt][0], acc[mt][nt][1]);
            float2 v1 = make_float2(acc[mt][nt][2], acc[mt][nt][3]);
            if (roundOut) {
                v0.x = tf32r(v0.x); v0.y = tf32r(v0.y);
                v1.x = tf32r(v1.x); v1.y = tf32r(v1.y);
            }
            *(float2*)&C[(size_t)row * N + col] = v0;
            *(float2*)&C[(size_t)(row + 8) * N + col] = v1;
        }
    }
}

// ---------------- BD band GEMM: g_bd[bh][i][m] = q_i . rk[m] + biasr[h][m] ----------------
// heads/rk are tf32-pre-rounded. Both K-chunks cp.async'd up-front (2 stages).
constexpr int BD_SMEM = 2 * 2 * GSTG * 4;   // 73728 bytes

__global__ __launch_bounds__(256)
void gemm_bd(const float* __restrict__ heads, const float* __restrict__ rkb,
             const float* __restrict__ brv, float* __restrict__ gbd) {
    const int It = blockIdx.y, Mt = blockIdx.x;
    if (It + Mt < 7) return;
    const int bh = blockIdx.z, b = bh >> 4, h = bh & 15;

    extern __shared__ float smx[];
    float* a_s = smx;                   // [2][GSTG]
    float* b_s = smx + 2 * GSTG;        // [2][GSTG]
    const uint32_t a_sb = (uint32_t)__cvta_generic_to_shared(a_s);
    const uint32_t b_sb = (uint32_t)__cvta_generic_to_shared(b_s);

    const int t = threadIdx.x;
    const int wid = t >> 5, lane = t & 31;
    const int wr = wid >> 2, wc = wid & 3;
    const int qrow = lane >> 2, qcol = lane & 3;
    const int row0 = It * 128, col0 = Mt * 128;

    const int lr = t >> 3;
    const int kq = (t & 7) * 4;

    // issue both chunks
    #pragma unroll
    for (int c = 0; c < 2; c++) {
        const int k0 = c * KC;
        #pragma unroll
        for (int i = 0; i < 4; i++) {
            const int r2 = lr + i * 32;
            const uint32_t soff = (uint32_t)(c * GSTG + r2 * SM_PITCH + kq) * 4;
            cp16(a_sb + soff,
                 &heads[((size_t)(row0 + r2) * BS + b) * HCOLS + h * 64 + k0 + kq]);
            cp16(b_sb + soff,
                 &rkb[(size_t)(col0 + r2) * DMODEL + h * 64 + k0 + kq]);
        }
        CP_COMMIT();
    }

    float acc[4][4][4] = {};

    #pragma unroll
    for (int c = 0; c < 2; c++) {
        if (c == 0) CP_WAIT1(); else CP_WAIT0();
        __syncthreads();
        const float* av = a_s + c * GSTG;
        const float* bv = b_s + c * GSTG;
        #pragma unroll
        for (int ks = 0; ks < KC / 8; ks++) {
            const int kk = ks * 8;
            uint32_t af[4][4], bf[4][2];
            #pragma unroll
            for (int mt = 0; mt < 4; mt++) {
                const int r0 = wr * 64 + mt * 16 + qrow;
                af[mt][0] = __float_as_uint(av[r0 * SM_PITCH + kk + qcol]);
                af[mt][1] = __float_as_uint(av[(r0 + 8) * SM_PITCH + kk + qcol]);
                af[mt][2] = __float_as_uint(av[r0 * SM_PITCH + kk + qcol + 4]);
                af[mt][3] = __float_as_uint(av[(r0 + 8) * SM_PITCH + kk + qcol + 4]);
            }
            #pragma unroll
            for (int nt = 0; nt < 4; nt++) {
                const int n0 = wc * 32 + nt * 8 + qrow;
                bf[nt][0] = __float_as_uint(bv[n0 * SM_PITCH + kk + qcol]);
                bf[nt][1] = __float_as_uint(bv[n0 * SM_PITCH + kk + qcol + 4]);
            }
            #pragma unroll
            for (int mt = 0; mt < 4; mt++)
                #pragma unroll
                for (int nt = 0; nt < 4; nt++)
                    mma_tf32(acc[mt][nt], af[mt], bf[nt]);
        }
    }

    float* gout = gbd + ((size_t)bh << 20);
    const float* br = brv + h * QL;
    #pragma unroll
    for (int mt = 0; mt < 4; mt++) {
        const int row = row0 + wr * 64 + mt * 16 + qrow;
        #pragma unroll
        for (int nt = 0; nt < 4; nt++) {
            const int col = col0 + wc * 32 + nt * 8 + qcol * 2;
            *(float2*)&gout[(size_t)row * 1024 + col] =
                make_float2(acc[mt][nt][0] + br[col], acc[mt][nt][1] + br[col + 1]);
            *(float2*)&gout[(size_t)(row + 8) * 1024 + col] =
                make_float2(acc[mt][nt][2] + br[col], acc[mt][nt][3] + br[col + 1]);
        }
    }
}

// ---------------- bias precompute ----------------
__global__ __launch_bounds__(256) void bias_k_kernel(const float* __restrict__ heads,
                                                     const float* __restrict__ rwb,
                                                     float* __restrict__ bk) {
    int gt = blockIdx.x * 256 + threadIdx.x;
    int wi = gt >> 5, lane = gt & 31;
    int j = wi & (QL - 1);
    int bh = wi >> 10;
    int b = bh >> 4, h = bh & 15;
    const float* kp = heads + ((size_t)j * BS + b) * HCOLS + 1024 + h * 64;
    const float* wp = rwb + h * 64;
    float s = kp[lane] * wp[lane] + kp[lane + 32] * wp[lane + 32];
    #pragma unroll
    for (int o = 16; o; o >>= 1) s += __shfl_xor_sync(0xffffffffu, s, o);
    if (lane == 0) bk[wi] = s;
}
__global__ __launch_bounds__(256) void bias_r_kernel(const float* __restrict__ rk,
                                                     const float* __restrict__ rrb,
                                                     float* __restrict__ brv) {
    int gt = blockIdx.x * 256 + threadIdx.x;
    int wi = gt >> 5, lane = gt & 31;
    int m = wi & (QL - 1);
    int h = wi >> 10;
    const float* rp = rk + (size_t)m * DMODEL + h * 64;
    const float* wp = rrb + h * 64;
    float s = rp[lane] * wp[lane] + rp[lane + 32] * wp[lane + 32];
    #pragma unroll
    for (int o = 16; o; o >>= 1) s += __shfl_xor_sync(0xffffffffu, s, o);
    if (lane == 0) brv[wi] = s;
}

// ---------------- tensor-core flash attention ----------------
// heads tf32-pre-rounded -> pure float4 tile copies, no cvt in loops.
constexpr int QP = 68;
constexpr int VP = 72;
constexpr int ATTN2_FLOATS = 128 * QP + 64 * QP + 64 * VP + 128 * QP + 64;
constexpr int ATTN2_BYTES  = ATTN2_FLOATS * 4;

__global__ __launch_bounds__(256)
void attn2(const float* __restrict__ heads, const float* __restrict__ biask,
           const float* __restrict__ gbd, float* __restrict__ vec) {
    extern __shared__ float sm[];
    float* q_s = sm;
    float* k_s = q_s + 128 * QP;
    float* v_s = k_s + 64 * QP;
    float* p_s = v_s + 64 * VP;
    float* bks = p_s + 128 * QP;

    const int bh = blockIdx.x, b = bh >> 4, h = bh & 15;
    const int ib = (int)gridDim.y - 1 - (int)blockIdx.y;
    const int i0 = ib * 128;
    const int t = threadIdx.x, wid = t >> 5, lane = t & 31;
    const int qr = lane >> 2, qc = lane & 3;
    const int rbase = wid * 16 + qr;

    // Q tile: 128x64, float4 (2048 float4s / 256 threads = 8 each)
    #pragma unroll
    for (int i = 0; i < 8; i++) {
        int e = t + i * 256;
        int ii = e >> 4, d4 = (e & 15) * 4;
        *(float4*)&q_s[ii * QP + d4] =
            *(const float4*)&heads[((size_t)(i0 + ii) * BS + b) * HCOLS + h * 64 + d4];
    }

    float oacc[8][4] = {};
    float m_run[2] = {-1e30f, -1e30f}, l_run[2] = {0.f, 0.f};
    const float* bk = biask + (size_t)(b * NHEAD + h) * QL;
    const size_t gbase = (size_t)bh << 20;

    const int njt = 2 * ib + 2;
    for (int jt = 0; jt < njt; jt++) {
        const int j0 = jt * 64;
        __syncthreads();
        // K/V tiles: 64x64 each, float4 (1024 float4s / 256 = 4 each)
        #pragma unroll
        for (int i = 0; i < 4; i++) {
            int e = t + i * 256;
            int jj = e >> 4, d4 = (e & 15) * 4;
            size_t base = ((size_t)(j0 + jj) * BS + b) * HCOLS + h * 64 + d4;
            *(float4*)&k_s[jj * QP + d4] = *(const float4*)&heads[base + 1024];
            *(float4*)&v_s[jj * VP + d4] = *(const float4*)&heads[base + 2048];
        }
        if (t < 64) bks[t] = bk[j0 + t];
        __syncthreads();

        float sacc[8][4] = {};
        #pragma unroll
        for (int ks = 0; ks < 8; ks++) {
            const int kk = ks * 8;
            uint32_t af[4];
            af[0] = __float_as_uint(q_s[rbase * QP + kk + qc]);
            af[1] = __float_as_uint(q_s[(rbase + 8) * QP + kk + qc]);
            af[2] = __float_as_uint(q_s[rbase * QP + kk + qc + 4]);
            af[3] = __float_as_uint(q_s[(rbase + 8) * QP + kk + qc + 4]);
            #pragma unroll
            for (int nt = 0; nt < 8; nt++) {
                uint32_t bf[2];
                bf[0] = __float_as_uint(k_s[(nt * 8 + qr) * QP + kk + qc]);
                bf[1] = __float_as_uint(k_s[(nt * 8 + qr) * QP + kk + qc + 4]);
                mma_tf32(sacc[nt], af, bf);
            }
        }

        #pragma unroll
        for (int s = 0; s < 2; s++) {
            const int ig = i0 + rbase + s * 8;
            const float* grow = gbd + gbase + (size_t)ig * 1024 + (1023 - ig + j0);
            #pragma unroll
            for (int nt = 0; nt < 8; nt++) {
                #pragma unroll
                for (int r = 0; r < 2; r++) {
                    const int jl = nt * 8 + qc * 2 + r;
                    const int jg = j0 + jl;
                    float v = sacc[nt][s * 2 + r];
                    if (jg <= ig) v = (v + bks[jl] + grow[jl]) * SCALE;
                    else          v = -1e30f;
                    sacc[nt][s * 2 + r] = v;
                }
            }
        }

        #pragma unroll
        for (int s = 0; s < 2; s++) {
            float mx = -1e30f;
            #pragma unroll
            for (int nt = 0; nt < 8; nt++)
                mx = fmaxf(mx, fmaxf(sacc[nt][s * 2], sacc[nt][s * 2 + 1]));
            mx = fmaxf(mx, __shfl_xor_sync(0xffffffffu, mx, 1));
            mx = fmaxf(mx, __shfl_xor_sync(0xffffffffu, mx, 2));
            float mnew = fmaxf(m_run[s], mx);
            float corr = __expf(m_run[s] - mnew);
            float rs = 0.f;
            #pragma unroll
            for (int nt = 0; nt < 8; nt++) {
                float p0 = __expf(sacc[nt][s * 2] - mnew);
                float p1 = __expf(sacc[nt][s * 2 + 1] - mnew);
                sacc[nt][s * 2] = p0; sacc[nt][s * 2 + 1] = p1;
                rs += p0 + p1;
            }
            rs += __shfl_xor_sync(0xffffffffu, rs, 1);
            rs += __shfl_xor_sync(0xffffffffu, rs, 2);
            l_run[s] = l_run[s] * corr + rs;
            m_run[s] = mnew;
            #pragma unroll
            for (int nt = 0; nt < 8; nt++) {
                oacc[nt][s * 2] *= corr;
                oacc[nt][s * 2 + 1] *= corr;
            }
        }

        #pragma unroll
        for (int s = 0; s < 2; s++) {
            #pragma unroll
            for (int nt = 0; nt < 8; nt++) {
                p_s[(rbase + s * 8) * QP + nt * 8 + qc * 2]     = tf32r(sacc[nt][s * 2]);
                p_s[(rbase + s * 8) * QP + nt * 8 + qc * 2 + 1] = tf32r(sacc[nt][s * 2 + 1]);
            }
        }
        __syncwarp();

        #pragma unroll
        for (int ks = 0; ks < 8; ks++) {
            uint32_t af[4];
            af[0] = __float_as_uint(p_s[rbase * QP + ks * 8 + qc]);
            af[1] = __float_as_uint(p_s[(rbase + 8) * QP + ks * 8 + qc]);
            af[2] = __float_as_uint(p_s[rbase * QP + ks * 8 + qc + 4]);
            af[3] = __float_as_uint(p_s[(rbase + 8) * QP + ks * 8 + qc + 4]);
            #pragma unroll
            for (int nt = 0; nt < 8; nt++) {
                uint32_t bf[2];
                bf[0] = __float_as_uint(v_s[(ks * 8 + qc) * VP + nt * 8 + qr]);
                bf[1] = __float_as_uint(v_s[(ks * 8 + qc + 4) * VP + nt * 8 + qr]);
                mma_tf32(oacc[nt], af, bf);
            }
        }
    }

    #pragma unroll
    for (int s = 0; s < 2; s++) {
        const int ig = i0 + rbase + s * 8;
        const float inv = 1.f / l_run[s];
        #pragma unroll
        for (int nt = 0; nt < 8; nt++) {
            float2 o2 = make_float2(tf32r(oacc[nt][s * 2] * inv),
                                    tf32r(oacc[nt][s * 2 + 1] * inv));
            *(float2*)&vec[((size_t)ig * BS + b) * DMODEL + h * 64 + nt * 8 + qc * 2] = o2;
        }
    }
}

// ---------------- residual + layernorm ----------------
__global__ __launch_bounds__(256) void ln_kernel(const float* __restrict__ w,
                                                 const float* __restrict__ proj,
                                                 const float* __restrict__ g,
                                                 const float* __restrict__ bta,
                                                 float* __restrict__ out) {
    __shared__ float red[8];
    const int row = blockIdx.x;
    const int t = threadIdx.x;
    const size_t base = (size_t)row * DMODEL;
    float x[4];
    float s = 0.f;
    #pragma unroll
    for (int u = 0; u < 4; u++) {
        int c = t + u * 256;
        x[u] = w[base + c] + proj[base + c];
        s += x[u];
    }
    #pragma unroll
    for (int o = 16; o; o >>= 1) s += __shfl_xor_sync(0xffffffffu, s, o);
    if ((t & 31) == 0) red[t >> 5] = s;
    __syncthreads();
    float tot = 0.f;
    #pragma unroll
    for (int i = 0; i < 8; i++) tot += red[i];
    const float mu = tot * (1.f / DMODEL);

    float vs = 0.f;
    #pragma unroll
    for (int u = 0; u < 4; u++) { float dd = x[u] - mu; vs += dd * dd; }
    #pragma unroll
    for (int o = 16; o; o >>= 1) vs += __shfl_xor_sync(0xffffffffu, vs, o);
    __syncthreads();
    if ((t & 31) == 0) red[t >> 5] = vs;
    __syncthreads();
    tot = 0.f;
    #pragma unroll
    for (int i = 0; i < 8; i++) tot += red[i];
    const float rstd = rsqrtf(tot * (1.f / DMODEL) + LNEPS);

    #pragma unroll
    for (int u = 0; u < 4; u++) {
        int c = t + u * 256;
        out[base + c] = (x[u] - mu) * rstd * g[c] + bta[c];
    }
}

// ---------------- launch ----------------
extern "C" void kernel_launch(void* const* d_in, const int* in_sizes, int n_in,
                              void* d_out, int out_size) {
    const float* w    = (const float*)d_in[0];
    const float* r    = (const float*)d_in[1];
    const float* qkvw = (const float*)d_in[3];
    const float* rw   = (const float*)d_in[4];
    const float* ow   = (const float*)d_in[5];
    const float* rrb  = (const float*)d_in[6];
    const float* rwb  = (const float*)d_in[7];
    const float* lng  = (const float*)d_in[8];
    const float* lnb  = (const float*)d_in[9];
    float* out = (float*)d_out;

    float *heads, *rkbuf, *bk, *brv, *vec, *proj, *qkvT, *rwT, *owT, *gbd, *wr, *rr;
    cudaGetSymbolAddress((void**)&heads, g_heads);
    cudaGetSymbolAddress((void**)&rkbuf, g_rk);
    cudaGetSymbolAddress((void**)&bk,    g_biask);
    cudaGetSymbolAddress((void**)&brv,   g_biasr);
    cudaGetSymbolAddress((void**)&vec,   g_vec);
    cudaGetSymbolAddress((void**)&proj,  g_proj);
    cudaGetSymbolAddress((void**)&qkvT,  g_qkvT);
    cudaGetSymbolAddress((void**)&rwT,   g_rwT);
    cudaGetSymbolAddress((void**)&owT,   g_owT);
    cudaGetSymbolAddress((void**)&gbd,   g_bd);
    cudaGetSymbolAddress((void**)&wr,    g_wr);
    cudaGetSymbolAddress((void**)&rr,    g_rr);

    cudaFuncSetAttribute(attn2, cudaFuncAttributeMaxDynamicSharedMemorySize, ATTN2_BYTES);
    cudaFuncSetAttribute(gemm_tf32, cudaFuncAttributeMaxDynamicSharedMemorySize, GEMM_SMEM);
    cudaFuncSetAttribute(gemm_bd, cudaFuncAttributeMaxDynamicSharedMemorySize, BD_SMEM);

    // 0) pre-round A operands; transpose + round weights to [N,K]
    round_copy<<<(NROWS * DMODEL / 4) / 256, 256>>>((const float4*)w, (float4*)wr,
                                                    NROWS * DMODEL / 4);
    round_copy<<<(QL * DMODEL / 4) / 256, 256>>>((const float4*)r, (float4*)rr,
                                                 QL * DMODEL / 4);
    transpose_k<<<dim3(HCOLS / 32, DMODEL / 32), dim3(32, 8)>>>(qkvw, qkvT, DMODEL, HCOLS);
    transpose_k<<<dim3(DMODEL / 32, DMODEL / 32), dim3(32, 8)>>>(rw, rwT, DMODEL, DMODEL);
    transpose_k<<<dim3(DMODEL / 32, DMODEL / 32), dim3(32, 8)>>>(ow, owT, DMODEL, DMODEL);

    // 1) heads = w @ qkv_w ; r_k = r @ r_w   (outputs tf32-rounded)
    gemm_tf32<<<dim3(HCOLS / 128, NROWS / 128), 256, GEMM_SMEM>>>(
        wr, qkvT, heads, NROWS, HCOLS, DMODEL, 1);
    gemm_tf32<<<dim3(DMODEL / 128, QL / 128), 256, GEMM_SMEM>>>(
        rr, rwT, rkbuf, QL, DMODEL, DMODEL, 1);
    // 2) biases
    bias_k_kernel<<<(BS * NHEAD * QL * 32) / 256, 256>>>(heads, rwb, bk);
    bias_r_kernel<<<(NHEAD * QL * 32) / 256, 256>>>(rkbuf, rrb, brv);
    // 3) BD band
    gemm_bd<<<dim3(8, 8, 64), 256, BD_SMEM>>>(heads, rkbuf, brv, gbd);
    // 4) tensor-core flash attention (writes tf32-rounded vec)
    attn2<<<dim3(BS * NHEAD, QL / 128), 256, ATTN2_BYTES>>>(heads, bk, gbd, vec);
    // 5) proj = vec @ o_w   (output NOT rounded; feeds LN)
    gemm_tf32<<<dim3(DMODEL / 128, NROWS / 128), 256, GEMM_SMEM>>>(
        vec, owT, proj, NROWS, DMODEL, DMODEL, 0);
    // 6) out = LN(w + proj)
    ln_kernel<<<NROWS, 256>>>(w, proj, lng, lnb, out);
}

// round 12
// speedup vs baseline: 1.7265x; 1.1349x over previous
#include <cuda_runtime.h>
#include <cstdint>
#include <cstddef>

// ---------------- problem constants ----------------
constexpr int QL     = 1024;
constexpr int BS     = 4;
constexpr int DMODEL = 1024;
constexpr int NHEAD  = 16;
constexpr int NROWS  = QL * BS;           // 4096
constexpr int HCOLS  = 3 * NHEAD * 64;    // 3072
constexpr float SCALE = 0.125f;
constexpr float LNEPS = 1e-5f;

// ---------------- scratch ----------------
__device__ float g_heads[(size_t)NROWS * HCOLS];
__device__ float g_rk[(size_t)QL * DMODEL];
__device__ float g_biask[BS * NHEAD * QL];
__device__ float g_biasr[NHEAD * QL];
__device__ float g_vec[(size_t)NROWS * DMODEL];
__device__ float g_proj[(size_t)NROWS * DMODEL];
__device__ float g_bd[(size_t)64 * 1024 * 1024];   // G[bh][i][m] band scores
__device__ float g_wr[(size_t)NROWS * DMODEL];     // tf32-rounded w
__device__ float g_rr[(size_t)QL * DMODEL];        // tf32-rounded r

__device__ __forceinline__ float tf32r(float x) {
    float y;
    asm("cvt.rna.tf32.f32 %0, %1;" : "=f"(y) : "f"(x));
    return y;
}
__device__ __forceinline__ void mma_tf32(float* d, const uint32_t* a, const uint32_t* b) {
    asm volatile(
        "mma.sync.aligned.m16n8k8.row.col.f32.tf32.tf32.f32 "
        "{%0,%1,%2,%3}, {%4,%5,%6,%7}, {%8,%9}, {%0,%1,%2,%3};\n"
        : "+f"(d[0]), "+f"(d[1]), "+f"(d[2]), "+f"(d[3])
        : "r"(a[0]), "r"(a[1]), "r"(a[2]), "r"(a[3]), "r"(b[0]), "r"(b[1]));
}
__device__ __forceinline__ void cp16(uint32_t saddr, const void* g) {
    asm volatile("cp.async.cg.shared.global [%0], [%1], 16;" :: "r"(saddr), "l"(g));
}
#define CP_COMMIT() asm volatile("cp.async.commit_group;" ::: "memory")
#define CP_WAIT1()  asm volatile("cp.async.wait_group 1;" ::: "memory")
#define CP_WAIT0()  asm volatile("cp.async.wait_group 0;" ::: "memory")

// ---------------- fused tf32 round-copy (w and r in one launch) ----------------
__global__ __launch_bounds__(256) void round_copy2(const float4* __restrict__ w,
                                                   float4* __restrict__ wr, int n4w,
                                                   const float4* __restrict__ r,
                                                   float4* __restrict__ rr, int n4r) {
    int i = blockIdx.x * 256 + threadIdx.x;
    if (i < n4w) {
        float4 v = w[i];
        v.x = tf32r(v.x); v.y = tf32r(v.y); v.z = tf32r(v.z); v.w = tf32r(v.w);
        wr[i] = v;
    } else {
        int j = i - n4w;
        if (j < n4r) {
            float4 v = r[j];
            v.x = tf32r(v.x); v.y = tf32r(v.y); v.z = tf32r(v.z); v.w = tf32r(v.w);
            rr[j] = v;
        }
    }
}

// ---------------- 2-stage cp.async tf32 GEMM core: C = A[M,K] @ B[K,N] ----------------
// A row-major, tf32-pre-rounded. B row-major RAW (HW truncation to tf32).
// CTA 128x128, 8 warps 2x4, warp 64x32, K-chunk 32.
constexpr int KC   = 32;
constexpr int AP   = 36;            // A smem pitch (floats)
constexpr int BP   = 136;           // B smem pitch (floats) -> conflict-free frag LDS
constexpr int ASTG = 128 * AP;      // 4608 floats / stage
constexpr int BSTG = KC * BP;       // 4352 floats / stage
constexpr int GEMM_SMEM = 2 * (ASTG + BSTG) * 4;   // 71680 bytes -> 2 CTAs/SM

__device__ __forceinline__ void gemm_core(const float* __restrict__ A,
                                          const float* __restrict__ B,
                                          float* __restrict__ C,
                                          int N, int K, int row0, int col0,
                                          int roundOut, float* smx) {
    float* a_s = smx;                      // [2][ASTG]
    float* b_s = smx + 2 * ASTG;           // [2][BSTG], layout [k][n]
    const uint32_t a_sb = (uint32_t)__cvta_generic_to_shared(a_s);
    const uint32_t b_sb = (uint32_t)__cvta_generic_to_shared(b_s);

    const int t = threadIdx.x;
    const int wid = t >> 5, lane = t & 31;
    const int wr = wid >> 2, wc = wid & 3;
    const int qrow = lane >> 2, qcol = lane & 3;
    const int lr = t >> 3;                 // 0..31
    const int kq = (t & 7) * 4;

    float acc[4][4][4] = {};

    auto load_chunk = [&](int c, int s) {
        const int k0 = c * KC;
        #pragma unroll
        for (int i = 0; i < 4; i++) {
            const int r2 = lr + i * 32;
            cp16(a_sb + (uint32_t)(s * ASTG + r2 * AP + kq) * 4,
                 &A[(size_t)(row0 + r2) * K + k0 + kq]);
            const int c2 = t + i * 256;                 // B: 32 rows x 128 cols
            const int kr = c2 >> 5, nc = (c2 & 31) * 4;
            cp16(b_sb + (uint32_t)(s * BSTG + kr * BP + nc) * 4,
                 &B[(size_t)(k0 + kr) * N + col0 + nc]);
        }
        CP_COMMIT();
    };

    const int NC = K / KC;
    load_chunk(0, 0);

    for (int c = 0; c < NC; c++) {
        const int s = c & 1;
        if (c + 1 < NC) { load_chunk(c + 1, s ^ 1); CP_WAIT1(); }
        else            { CP_WAIT0(); }
        __syncthreads();

        const float* av = a_s + s * ASTG;
        const float* bv = b_s + s * BSTG;
        #pragma unroll
        for (int ks = 0; ks < KC / 8; ks++) {
            const int kk = ks * 8;
            uint32_t af[4][4], bf[4][2];
            #pragma unroll
            for (int mt = 0; mt < 4; mt++) {
                const int r0 = wr * 64 + mt * 16 + qrow;
                af[mt][0] = __float_as_uint(av[r0 * AP + kk + qcol]);
                af[mt][1] = __float_as_uint(av[(r0 + 8) * AP + kk + qcol]);
                af[mt][2] = __float_as_uint(av[r0 * AP + kk + qcol + 4]);
                af[mt][3] = __float_as_uint(av[(r0 + 8) * AP + kk + qcol + 4]);
            }
            #pragma unroll
            for (int nt = 0; nt < 4; nt++) {
                const int n0 = wc * 32 + nt * 8 + qrow;
                bf[nt][0] = __float_as_uint(bv[(kk + qcol) * BP + n0]);
                bf[nt][1] = __float_as_uint(bv[(kk + qcol + 4) * BP + n0]);
            }
            #pragma unroll
            for (int mt = 0; mt < 4; mt++)
                #pragma unroll
                for (int nt = 0; nt < 4; nt++)
                    mma_tf32(acc[mt][nt], af[mt], bf[nt]);
        }
        __syncthreads();
    }

    #pragma unroll
    for (int mt = 0; mt < 4; mt++) {
        const int row = row0 + wr * 64 + mt * 16 + qrow;
        #pragma unroll
        for (int nt = 0; nt < 4; nt++) {
            const int col = col0 + wc * 32 + nt * 8 + qcol * 2;
            float2 v0 = make_float2(acc[mt][nt][0], acc[mt][nt][1]);
            float2 v1 = make_float2(acc[mt][nt][2], acc[mt][nt][3]);
            if (roundOut) {
                v0.x = tf32r(v0.x); v0.y = tf32r(v0.y);
                v1.x = tf32r(v1.x); v1.y = tf32r(v1.y);
            }
            *(float2*)&C[(size_t)row * N + col] = v0;
            *(float2*)&C[(size_t)(row + 8) * N + col] = v1;
        }
    }
}

// generic wrapper (proj)
__global__ __launch_bounds__(256, 2)
void gemm_tf32(const float* __restrict__ A, const float* __restrict__ B,
               float* __restrict__ C, int N, int K, int roundOut) {
    extern __shared__ float smx[];
    gemm_core(A, B, C, N, K, blockIdx.y * 128, blockIdx.x * 128, roundOut, smx);
}

// fused qkv + rk launch: grid (24, 40); by<32 -> qkv tile, else rk tile
__global__ __launch_bounds__(256, 2)
void gemm_qkv_rk(const float* __restrict__ wr_, const float* __restrict__ qkvw,
                 float* __restrict__ heads,
                 const float* __restrict__ rr_, const float* __restrict__ rw,
                 float* __restrict__ rkbuf) {
    extern __shared__ float smx[];
    const float *A, *B; float* C; int N, K, row0, col0;
    if (blockIdx.y < 32) {
        A = wr_; B = qkvw; C = heads; N = HCOLS; K = DMODEL;
        row0 = blockIdx.y * 128; col0 = blockIdx.x * 128;
    } else {
        if (blockIdx.x >= 8) return;
        A = rr_; B = rw; C = rkbuf; N = DMODEL; K = DMODEL;
        row0 = (blockIdx.y - 32) * 128; col0 = blockIdx.x * 128;
    }
    gemm_core(A, B, C, N, K, row0, col0, 1, smx);
}

// ---------------- BD band GEMM (unchanged, measured-good): gbd[bh][i][m] = q_i.rk[m] + biasr ----------------
constexpr int SM_PITCH = 36;
constexpr int GSTG = 128 * SM_PITCH;
constexpr int BD_SMEM = 2 * 2 * GSTG * 4;   // 73728 bytes

__global__ __launch_bounds__(256)
void gemm_bd(const float* __restrict__ heads, const float* __restrict__ rkb,
             const float* __restrict__ brv, float* __restrict__ gbd) {
    const int It = blockIdx.y, Mt = blockIdx.x;
    if (It + Mt < 7) return;
    const int bh = blockIdx.z, b = bh >> 4, h = bh & 15;

    extern __shared__ float smx[];
    float* a_s = smx;
    float* b_s = smx + 2 * GSTG;
    const uint32_t a_sb = (uint32_t)__cvta_generic_to_shared(a_s);
    const uint32_t b_sb = (uint32_t)__cvta_generic_to_shared(b_s);

    const int t = threadIdx.x;
    const int wid = t >> 5, lane = t & 31;
    const int wr = wid >> 2, wc = wid & 3;
    const int qrow = lane >> 2, qcol = lane & 3;
    const int row0 = It * 128, col0 = Mt * 128;

    const int lr = t >> 3;
    const int kq = (t & 7) * 4;

    #pragma unroll
    for (int c = 0; c < 2; c++) {
        const int k0 = c * KC;
        #pragma unroll
        for (int i = 0; i < 4; i++) {
            const int r2 = lr + i * 32;
            const uint32_t soff = (uint32_t)(c * GSTG + r2 * SM_PITCH + kq) * 4;
            cp16(a_sb + soff,
                 &heads[((size_t)(row0 + r2) * BS + b) * HCOLS + h * 64 + k0 + kq]);
            cp16(b_sb + soff,
                 &rkb[(size_t)(col0 + r2) * DMODEL + h * 64 + k0 + kq]);
        }
        CP_COMMIT();
    }

    float acc[4][4][4] = {};

    #pragma unroll
    for (int c = 0; c < 2; c++) {
        if (c == 0) CP_WAIT1(); else CP_WAIT0();
        __syncthreads();
        const float* av = a_s + c * GSTG;
        const float* bv = b_s + c * GSTG;
        #pragma unroll
        for (int ks = 0; ks < KC / 8; ks++) {
            const int kk = ks * 8;
            uint32_t af[4][4], bf[4][2];
            #pragma unroll
            for (int mt = 0; mt < 4; mt++) {
                const int r0 = wr * 64 + mt * 16 + qrow;
                af[mt][0] = __float_as_uint(av[r0 * SM_PITCH + kk + qcol]);
                af[mt][1] = __float_as_uint(av[(r0 + 8) * SM_PITCH + kk + qcol]);
                af[mt][2] = __float_as_uint(av[r0 * SM_PITCH + kk + qcol + 4]);
                af[mt][3] = __float_as_uint(av[(r0 + 8) * SM_PITCH + kk + qcol + 4]);
            }
            #pragma unroll
            for (int nt = 0; nt < 4; nt++) {
                const int n0 = wc * 32 + nt * 8 + qrow;
                bf[nt][0] = __float_as_uint(bv[n0 * SM_PITCH + kk + qcol]);
                bf[nt][1] = __float_as_uint(bv[n0 * SM_PITCH + kk + qcol + 4]);
            }
            #pragma unroll
            for (int mt = 0; mt < 4; mt++)
                #pragma unroll
                for (int nt = 0; nt < 4; nt++)
                    mma_tf32(acc[mt][nt], af[mt], bf[nt]);
        }
    }

    float* gout = gbd + ((size_t)bh << 20);
    const float* br = brv + h * QL;
    #pragma unroll
    for (int mt = 0; mt < 4; mt++) {
        const int row = row0 + wr * 64 + mt * 16 + qrow;
        #pragma unroll
        for (int nt = 0; nt < 4; nt++) {
            const int col = col0 + wc * 32 + nt * 8 + qcol * 2;
            *(float2*)&gout[(size_t)row * 1024 + col] =
                make_float2(acc[mt][nt][0] + br[col], acc[mt][nt][1] + br[col + 1]);
            *(float2*)&gout[(size_t)(row + 8) * 1024 + col] =
                make_float2(acc[mt][nt][2] + br[col], acc[mt][nt][3] + br[col + 1]);
        }
    }
}

// ---------------- bias precompute ----------------
__global__ __launch_bounds__(256) void bias_k_kernel(const float* __restrict__ heads,
                                                     const float* __restrict__ rwb,
                                                     float* __restrict__ bk) {
    int gt = blockIdx.x * 256 + threadIdx.x;
    int wi = gt >> 5, lane = gt & 31;
    int j = wi & (QL - 1);
    int bh = wi >> 10;
    int b = bh >> 4, h = bh & 15;
    const float* kp = heads + ((size_t)j * BS + b) * HCOLS + 1024 + h * 64;
    const float* wp = rwb + h * 64;
    float s = kp[lane] * wp[lane] + kp[lane + 32] * wp[lane + 32];
    #pragma unroll
    for (int o = 16; o; o >>= 1) s += __shfl_xor_sync(0xffffffffu, s, o);
    if (lane == 0) bk[wi] = s;
}
__global__ __launch_bounds__(256) void bias_r_kernel(const float* __restrict__ rk,
                                                     const float* __restrict__ rrb,
                                                     float* __restrict__ brv) {
    int gt = blockIdx.x * 256 + threadIdx.x;
    int wi = gt >> 5, lane = gt & 31;
    int m = wi & (QL - 1);
    int h = wi >> 10;
    const float* rp = rk + (size_t)m * DMODEL + h * 64;
    const float* wp = rrb + h * 64;
    float s = rp[lane] * wp[lane] + rp[lane + 32] * wp[lane + 32];
    #pragma unroll
    for (int o = 16; o; o >>= 1) s += __shfl_xor_sync(0xffffffffu, s, o);
    if (lane == 0) brv[wi] = s;
}

// ---------------- tensor-core flash attention (unchanged, measured-good) ----------------
constexpr int QP = 68;
constexpr int VP = 72;
constexpr int ATTN2_FLOATS = 128 * QP + 64 * QP + 64 * VP + 128 * QP + 64;
constexpr int ATTN2_BYTES  = ATTN2_FLOATS * 4;

__global__ __launch_bounds__(256)
void attn2(const float* __restrict__ heads, const float* __restrict__ biask,
           const float* __restrict__ gbd, float* __restrict__ vec) {
    extern __shared__ float sm[];
    float* q_s = sm;
    float* k_s = q_s + 128 * QP;
    float* v_s = k_s + 64 * QP;
    float* p_s = v_s + 64 * VP;
    float* bks = p_s + 128 * QP;

    const int bh = blockIdx.x, b = bh >> 4, h = bh & 15;
    const int ib = (int)gridDim.y - 1 - (int)blockIdx.y;
    const int i0 = ib * 128;
    const int t = threadIdx.x, wid = t >> 5, lane = t & 31;
    const int qr = lane >> 2, qc = lane & 3;
    const int rbase = wid * 16 + qr;

    #pragma unroll
    for (int i = 0; i < 8; i++) {
        int e = t + i * 256;
        int ii = e >> 4, d4 = (e & 15) * 4;
        *(float4*)&q_s[ii * QP + d4] =
            *(const float4*)&heads[((size_t)(i0 + ii) * BS + b) * HCOLS + h * 64 + d4];
    }

    float oacc[8][4] = {};
    float m_run[2] = {-1e30f, -1e30f}, l_run[2] = {0.f, 0.f};
    const float* bk = biask + (size_t)(b * NHEAD + h) * QL;
    const size_t gbase = (size_t)bh << 20;

    const int njt = 2 * ib + 2;
    for (int jt = 0; jt < njt; jt++) {
        const int j0 = jt * 64;
        __syncthreads();
        #pragma unroll
        for (int i = 0; i < 4; i++) {
            int e = t + i * 256;
            int jj = e >> 4, d4 = (e & 15) * 4;
            size_t base = ((size_t)(j0 + jj) * BS + b) * HCOLS + h * 64 + d4;
            *(float4*)&k_s[jj * QP + d4] = *(const float4*)&heads[base + 1024];
            *(float4*)&v_s[jj * VP + d4] = *(const float4*)&heads[base + 2048];
        }
        if (t < 64) bks[t] = bk[j0 + t];
        __syncthreads();

        float sacc[8][4] = {};
        #pragma unroll
        for (int ks = 0; ks < 8; ks++) {
            const int kk = ks * 8;
            uint32_t af[4];
            af[0] = __float_as_uint(q_s[rbase * QP + kk + qc]);
            af[1] = __float_as_uint(q_s[(rbase + 8) * QP + kk + qc]);
            af[2] = __float_as_uint(q_s[rbase * QP + kk + qc + 4]);
            af[3] = __float_as_uint(q_s[(rbase + 8) * QP + kk + qc + 4]);
            #pragma unroll
            for (int nt = 0; nt < 8; nt++) {
                uint32_t bf[2];
                bf[0] = __float_as_uint(k_s[(nt * 8 + qr) * QP + kk + qc]);
                bf[1] = __float_as_uint(k_s[(nt * 8 + qr) * QP + kk + qc + 4]);
                mma_tf32(sacc[nt], af, bf);
            }
        }

        #pragma unroll
        for (int s = 0; s < 2; s++) {
            const int ig = i0 + rbase + s * 8;
            const float* grow = gbd + gbase + (size_t)ig * 1024 + (1023 - ig + j0);
            #pragma unroll
            for (int nt = 0; nt < 8; nt++) {
                #pragma unroll
                for (int r = 0; r < 2; r++) {
                    const int jl = nt * 8 + qc * 2 + r;
                    const int jg = j0 + jl;
                    float v = sacc[nt][s * 2 + r];
                    if (jg <= ig) v = (v + bks[jl] + grow[jl]) * SCALE;
                    else          v = -1e30f;
                    sacc[nt][s * 2 + r] = v;
                }
            }
        }

        #pragma unroll
        for (int s = 0; s < 2; s++) {
            float mx = -1e30f;
            #pragma unroll
            for (int nt = 0; nt < 8; nt++)
                mx = fmaxf(mx, fmaxf(sacc[nt][s * 2], sacc[nt][s * 2 + 1]));
            mx = fmaxf(mx, __shfl_xor_sync(0xffffffffu, mx, 1));
            mx = fmaxf(mx, __shfl_xor_sync(0xffffffffu, mx, 2));
            float mnew = fmaxf(m_run[s], mx);
            float corr = __expf(m_run[s] - mnew);
            float rs = 0.f;
            #pragma unroll
            for (int nt = 0; nt < 8; nt++) {
                float p0 = __expf(sacc[nt][s * 2] - mnew);
                float p1 = __expf(sacc[nt][s * 2 + 1] - mnew);
                sacc[nt][s * 2] = p0; sacc[nt][s * 2 + 1] = p1;
                rs += p0 + p1;
            }
            rs += __shfl_xor_sync(0xffffffffu, rs, 1);
            rs += __shfl_xor_sync(0xffffffffu, rs, 2);
            l_run[s] = l_run[s] * corr + rs;
            m_run[s] = mnew;
            #pragma unroll
            for (int nt = 0; nt < 8; nt++) {
                oacc[nt][s * 2] *= corr;
                oacc[nt][s * 2 + 1] *= corr;
            }
        }

        #pragma unroll
        for (int s = 0; s < 2; s++) {
            #pragma unroll
            for (int nt = 0; nt < 8; nt++) {
                p_s[(rbase + s * 8) * QP + nt * 8 + qc * 2]     = tf32r(sacc[nt][s * 2]);
                p_s[(rbase + s * 8) * QP + nt * 8 + qc * 2 + 1] = tf32r(sacc[nt][s * 2 + 1]);
            }
        }
        __syncwarp();

        #pragma unroll
        for (int ks = 0; ks < 8; ks++) {
            uint32_t af[4];
            af[0] = __float_as_uint(p_s[rbase * QP + ks * 8 + qc]);
            af[1] = __float_as_uint(p_s[(rbase + 8) * QP + ks * 8 + qc]);
            af[2] = __float_as_uint(p_s[rbase * QP + ks * 8 + qc + 4]);
            af[3] = __float_as_uint(p_s[(rbase + 8) * QP + ks * 8 + qc + 4]);
            #pragma unroll
            for (int nt = 0; nt < 8; nt++) {
                uint32_t bf[2];
                bf[0] = __float_as_uint(v_s[(ks * 8 + qc) * VP + nt * 8 + qr]);
                bf[1] = __float_as_uint(v_s[(ks * 8 + qc + 4) * VP + nt * 8 + qr]);
                mma_tf32(oacc[nt], af, bf);
            }
        }
    }

    #pragma unroll
    for (int s = 0; s < 2; s++) {
        const int ig = i0 + rbase + s * 8;
        const float inv = 1.f / l_run[s];
        #pragma unroll
        for (int nt = 0; nt < 8; nt++) {
            float2 o2 = make_float2(tf32r(oacc[nt][s * 2] * inv),
                                    tf32r(oacc[nt][s * 2 + 1] * inv));
            *(float2*)&vec[((size_t)ig * BS + b) * DMODEL + h * 64 + nt * 8 + qc * 2] = o2;
        }
    }
}

// ---------------- residual + layernorm ----------------
__global__ __launch_bounds__(256) void ln_kernel(const float* __restrict__ w,
                                                 const float* __restrict__ proj,
                                                 const float* __restrict__ g,
                                                 const float* __restrict__ bta,
                                                 float* __restrict__ out) {
    __shared__ float red[8];
    const int row = blockIdx.x;
    const int t = threadIdx.x;
    const size_t base = (size_t)row * DMODEL;
    float x[4];
    float s = 0.f;
    #pragma unroll
    for (int u = 0; u < 4; u++) {
        int c = t + u * 256;
        x[u] = w[base + c] + proj[base + c];
        s += x[u];
    }
    #pragma unroll
    for (int o = 16; o; o >>= 1) s += __shfl_xor_sync(0xffffffffu, s, o);
    if ((t & 31) == 0) red[t >> 5] = s;
    __syncthreads();
    float tot = 0.f;
    #pragma unroll
    for (int i = 0; i < 8; i++) tot += red[i];
    const float mu = tot * (1.f / DMODEL);

    float vs = 0.f;
    #pragma unroll
    for (int u = 0; u < 4; u++) { float dd = x[u] - mu; vs += dd * dd; }
    #pragma unroll
    for (int o = 16; o; o >>= 1) vs += __shfl_xor_sync(0xffffffffu, vs, o);
    __syncthreads();
    if ((t & 31) == 0) red[t >> 5] = vs;
    __syncthreads();
    tot = 0.f;
    #pragma unroll
    for (int i = 0; i < 8; i++) tot += red[i];
    const float rstd = rsqrtf(tot * (1.f / DMODEL) + LNEPS);

    #pragma unroll
    for (int u = 0; u < 4; u++) {
        int c = t + u * 256;
        out[base + c] = (x[u] - mu) * rstd * g[c] + bta[c];
    }
}

// ---------------- launch ----------------
extern "C" void kernel_launch(void* const* d_in, const int* in_sizes, int n_in,
                              void* d_out, int out_size) {
    const float* w    = (const float*)d_in[0];
    const float* r    = (const float*)d_in[1];
    const float* qkvw = (const float*)d_in[3];
    const float* rw   = (const float*)d_in[4];
    const float* ow   = (const float*)d_in[5];
    const float* rrb  = (const float*)d_in[6];
    const float* rwb  = (const float*)d_in[7];
    const float* lng  = (const float*)d_in[8];
    const float* lnb  = (const float*)d_in[9];
    float* out = (float*)d_out;

    float *heads, *rkbuf, *bk, *brv, *vec, *proj, *gbd, *wr, *rr;
    cudaGetSymbolAddress((void**)&heads, g_heads);
    cudaGetSymbolAddress((void**)&rkbuf, g_rk);
    cudaGetSymbolAddress((void**)&bk,    g_biask);
    cudaGetSymbolAddress((void**)&brv,   g_biasr);
    cudaGetSymbolAddress((void**)&vec,   g_vec);
    cudaGetSymbolAddress((void**)&proj,  g_proj);
    cudaGetSymbolAddress((void**)&gbd,   g_bd);
    cudaGetSymbolAddress((void**)&wr,    g_wr);
    cudaGetSymbolAddress((void**)&rr,    g_rr);

    cudaFuncSetAttribute(attn2, cudaFuncAttributeMaxDynamicSharedMemorySize, ATTN2_BYTES);
    cudaFuncSetAttribute(gemm_tf32, cudaFuncAttributeMaxDynamicSharedMemorySize, GEMM_SMEM);
    cudaFuncSetAttribute(gemm_qkv_rk, cudaFuncAttributeMaxDynamicSharedMemorySize, GEMM_SMEM);
    cudaFuncSetAttribute(gemm_bd, cudaFuncAttributeMaxDynamicSharedMemorySize, BD_SMEM);

    // 0) pre-round A operands (w, r) in one launch
    const int n4w = NROWS * DMODEL / 4, n4r = QL * DMODEL / 4;
    round_copy2<<<(n4w + n4r) / 256, 256>>>((const float4*)w, (float4*)wr, n4w,
                                            (const float4*)r, (float4*)rr, n4r);

    // 1) fused: heads = w @ qkv_w  AND  r_k = r @ r_w  (B raw row-major; outputs rounded)
    gemm_qkv_rk<<<dim3(24, 40), 256, GEMM_SMEM>>>(wr, qkvw, heads, rr, rw, rkbuf);

    // 2) biases
    bias_k_kernel<<<(BS * NHEAD * QL * 32) / 256, 256>>>(heads, rwb, bk);
    bias_r_kernel<<<(NHEAD * QL * 32) / 256, 256>>>(rkbuf, rrb, brv);

    // 3) BD band
    gemm_bd<<<dim3(8, 8, 64), 256, BD_SMEM>>>(heads, rkbuf, brv, gbd);

    // 4) tensor-core flash attention (writes tf32-rounded vec)
    attn2<<<dim3(BS * NHEAD, QL / 128), 256, ATTN2_BYTES>>>(heads, bk, gbd, vec);

    // 5) proj = vec @ o_w (B raw row-major; output NOT rounded; feeds LN)
    gemm_tf32<<<dim3(DMODEL / 128, NROWS / 128), 256, GEMM_SMEM>>>(
        vec, ow, proj, DMODEL, DMODEL, 0);

    // 6) out = LN(w + proj)
    ln_kernel<<<NROWS, 256>>>(w, proj, lng, lnb, out);
}

// round 13
// speedup vs baseline: 1.7613x; 1.0202x over previous
#include <cuda_runtime.h>
#include <cuda_fp16.h>
#include <cstdint>
#include <cstddef>

// ---------------- problem constants ----------------
constexpr int QL     = 1024;
constexpr int BS     = 4;
constexpr int DMODEL = 1024;
constexpr int NHEAD  = 16;
constexpr int NROWS  = QL * BS;           // 4096
constexpr int HCOLS  = 3 * NHEAD * 64;    // 3072
constexpr float SCALE = 0.125f;
constexpr float LNEPS = 1e-5f;

// ---------------- scratch ----------------
__device__ float  g_heads[(size_t)NROWS * HCOLS];
__device__ float  g_rk[(size_t)QL * DMODEL];
__device__ float  g_biask[BS * NHEAD * QL];
__device__ float  g_biasr[NHEAD * QL];
__device__ float  g_vec[(size_t)NROWS * DMODEL];
__device__ float  g_proj[(size_t)NROWS * DMODEL];
__device__ __half g_bd[(size_t)64 * 1024 * 1024];   // G[bh][i][m] band scores (fp16)

__device__ __forceinline__ float tf32r(float x) {
    float y;
    asm("cvt.rna.tf32.f32 %0, %1;" : "=f"(y) : "f"(x));
    return y;
}
__device__ __forceinline__ void mma_tf32(float* d, const uint32_t* a, const uint32_t* b) {
    asm volatile(
        "mma.sync.aligned.m16n8k8.row.col.f32.tf32.tf32.f32 "
        "{%0,%1,%2,%3}, {%4,%5,%6,%7}, {%8,%9}, {%0,%1,%2,%3};\n"
        : "+f"(d[0]), "+f"(d[1]), "+f"(d[2]), "+f"(d[3])
        : "r"(a[0]), "r"(a[1]), "r"(a[2]), "r"(a[3]), "r"(b[0]), "r"(b[1]));
}
__device__ __forceinline__ void cp16(uint32_t saddr, const void* g) {
    asm volatile("cp.async.cg.shared.global [%0], [%1], 16;" :: "r"(saddr), "l"(g));
}
#define CP_COMMIT() asm volatile("cp.async.commit_group;" ::: "memory")
#define CP_WAIT1()  asm volatile("cp.async.wait_group 1;" ::: "memory")
#define CP_WAIT0()  asm volatile("cp.async.wait_group 0;" ::: "memory")

// ---------------- 2-stage cp.async tf32 GEMM core: C = A[M,K] @ B[K,N] ----------------
// A and B row-major RAW f32 (HW rounds to tf32 in the mma).
// CTA 128x128, 8 warps 2x4, warp 64x32, K-chunk 32.
constexpr int KC   = 32;
constexpr int AP   = 36;            // A smem pitch (floats)
constexpr int BP   = 136;           // B smem pitch (floats) -> conflict-free frag LDS
constexpr int ASTG = 128 * AP;      // 4608 floats / stage
constexpr int BSTG = KC * BP;       // 4352 floats / stage
constexpr int GEMM_SMEM = 2 * (ASTG + BSTG) * 4;   // 71680 bytes -> 2 CTAs/SM

__device__ __forceinline__ void gemm_core(const float* __restrict__ A,
                                          const float* __restrict__ B,
                                          float* __restrict__ C,
                                          int N, int K, int row0, int col0,
                                          int roundOut, float* smx) {
    float* a_s = smx;                      // [2][ASTG]
    float* b_s = smx + 2 * ASTG;           // [2][BSTG], layout [k][n]
    const uint32_t a_sb = (uint32_t)__cvta_generic_to_shared(a_s);
    const uint32_t b_sb = (uint32_t)__cvta_generic_to_shared(b_s);

    const int t = threadIdx.x;
    const int wid = t >> 5, lane = t & 31;
    const int wr = wid >> 2, wc = wid & 3;
    const int qrow = lane >> 2, qcol = lane & 3;
    const int lr = t >> 3;                 // 0..31
    const int kq = (t & 7) * 4;

    float acc[4][4][4] = {};

    auto load_chunk = [&](int c, int s) {
        const int k0 = c * KC;
        #pragma unroll
        for (int i = 0; i < 4; i++) {
            const int r2 = lr + i * 32;
            cp16(a_sb + (uint32_t)(s * ASTG + r2 * AP + kq) * 4,
                 &A[(size_t)(row0 + r2) * K + k0 + kq]);
            const int c2 = t + i * 256;                 // B: 32 rows x 128 cols
            const int kr = c2 >> 5, nc = (c2 & 31) * 4;
            cp16(b_sb + (uint32_t)(s * BSTG + kr * BP + nc) * 4,
                 &B[(size_t)(k0 + kr) * N + col0 + nc]);
        }
        CP_COMMIT();
    };

    const int NC = K / KC;
    load_chunk(0, 0);

    for (int c = 0; c < NC; c++) {
        const int s = c & 1;
        if (c + 1 < NC) { load_chunk(c + 1, s ^ 1); CP_WAIT1(); }
        else            { CP_WAIT0(); }
        __syncthreads();

        const float* av = a_s + s * ASTG;
        const float* bv = b_s + s * BSTG;
        #pragma unroll
        for (int ks = 0; ks < KC / 8; ks++) {
            const int kk = ks * 8;
            uint32_t af[4][4], bf[4][2];
            #pragma unroll
            for (int mt = 0; mt < 4; mt++) {
                const int r0 = wr * 64 + mt * 16 + qrow;
                af[mt][0] = __float_as_uint(av[r0 * AP + kk + qcol]);
                af[mt][1] = __float_as_uint(av[(r0 + 8) * AP + kk + qcol]);
                af[mt][2] = __float_as_uint(av[r0 * AP + kk + qcol + 4]);
                af[mt][3] = __float_as_uint(av[(r0 + 8) * AP + kk + qcol + 4]);
            }
            #pragma unroll
            for (int nt = 0; nt < 4; nt++) {
                const int n0 = wc * 32 + nt * 8 + qrow;
                bf[nt][0] = __float_as_uint(bv[(kk + qcol) * BP + n0]);
                bf[nt][1] = __float_as_uint(bv[(kk + qcol + 4) * BP + n0]);
            }
            #pragma unroll
            for (int mt = 0; mt < 4; mt++)
                #pragma unroll
                for (int nt = 0; nt < 4; nt++)
                    mma_tf32(acc[mt][nt], af[mt], bf[nt]);
        }
        __syncthreads();
    }

    #pragma unroll
    for (int mt = 0; mt < 4; mt++) {
        const int row = row0 + wr * 64 + mt * 16 + qrow;
        #pragma unroll
        for (int nt = 0; nt < 4; nt++) {
            const int col = col0 + wc * 32 + nt * 8 + qcol * 2;
            float2 v0 = make_float2(acc[mt][nt][0], acc[mt][nt][1]);
            float2 v1 = make_float2(acc[mt][nt][2], acc[mt][nt][3]);
            if (roundOut) {
                v0.x = tf32r(v0.x); v0.y = tf32r(v0.y);
                v1.x = tf32r(v1.x); v1.y = tf32r(v1.y);
            }
            *(float2*)&C[(size_t)row * N + col] = v0;
            *(float2*)&C[(size_t)(row + 8) * N + col] = v1;
        }
    }
}

// generic wrapper (proj)
__global__ __launch_bounds__(256, 2)
void gemm_tf32(const float* __restrict__ A, const float* __restrict__ B,
               float* __restrict__ C, int N, int K, int roundOut) {
    extern __shared__ float smx[];
    gemm_core(A, B, C, N, K, blockIdx.y * 128, blockIdx.x * 128, roundOut, smx);
}

// fused qkv + rk launch: grid (24, 40); by<32 -> qkv tile, else rk tile
__global__ __launch_bounds__(256, 2)
void gemm_qkv_rk(const float* __restrict__ w, const float* __restrict__ qkvw,
                 float* __restrict__ heads,
                 const float* __restrict__ r, const float* __restrict__ rw,
                 float* __restrict__ rkbuf) {
    extern __shared__ float smx[];
    const float *A, *B; float* C; int N, K, row0, col0;
    if (blockIdx.y < 32) {
        A = w; B = qkvw; C = heads; N = HCOLS; K = DMODEL;
        row0 = blockIdx.y * 128; col0 = blockIdx.x * 128;
    } else {
        if (blockIdx.x >= 8) return;
        A = r; B = rw; C = rkbuf; N = DMODEL; K = DMODEL;
        row0 = (blockIdx.y - 32) * 128; col0 = blockIdx.x * 128;
    }
    gemm_core(A, B, C, N, K, row0, col0, 1, smx);
}

// ---------------- BD band GEMM: gbd[bh][i][m] = fp16(q_i.rk[m] + biasr[h][m]) ----------------
constexpr int SM_PITCH = 36;
constexpr int GSTG = 128 * SM_PITCH;
constexpr int BD_SMEM = 2 * 2 * GSTG * 4;   // 73728 bytes

__global__ __launch_bounds__(256)
void gemm_bd(const float* __restrict__ heads, const float* __restrict__ rkb,
             const float* __restrict__ brv, __half* __restrict__ gbd) {
    const int It = blockIdx.y, Mt = blockIdx.x;
    if (It + Mt < 7) return;
    const int bh = blockIdx.z, b = bh >> 4, h = bh & 15;

    extern __shared__ float smx[];
    float* a_s = smx;
    float* b_s = smx + 2 * GSTG;
    const uint32_t a_sb = (uint32_t)__cvta_generic_to_shared(a_s);
    const uint32_t b_sb = (uint32_t)__cvta_generic_to_shared(b_s);

    const int t = threadIdx.x;
    const int wid = t >> 5, lane = t & 31;
    const int wr = wid >> 2, wc = wid & 3;
    const int qrow = lane >> 2, qcol = lane & 3;
    const int row0 = It * 128, col0 = Mt * 128;

    const int lr = t >> 3;
    const int kq = (t & 7) * 4;

    #pragma unroll
    for (int c = 0; c < 2; c++) {
        const int k0 = c * KC;
        #pragma unroll
        for (int i = 0; i < 4; i++) {
            const int r2 = lr + i * 32;
            const uint32_t soff = (uint32_t)(c * GSTG + r2 * SM_PITCH + kq) * 4;
            cp16(a_sb + soff,
                 &heads[((size_t)(row0 + r2) * BS + b) * HCOLS + h * 64 + k0 + kq]);
            cp16(b_sb + soff,
                 &rkb[(size_t)(col0 + r2) * DMODEL + h * 64 + k0 + kq]);
        }
        CP_COMMIT();
    }

    float acc[4][4][4] = {};

    #pragma unroll
    for (int c = 0; c < 2; c++) {
        if (c == 0) CP_WAIT1(); else CP_WAIT0();
        __syncthreads();
        const float* av = a_s + c * GSTG;
        const float* bv = b_s + c * GSTG;
        #pragma unroll
        for (int ks = 0; ks < KC / 8; ks++) {
            const int kk = ks * 8;
            uint32_t af[4][4], bf[4][2];
            #pragma unroll
            for (int mt = 0; mt < 4; mt++) {
                const int r0 = wr * 64 + mt * 16 + qrow;
                af[mt][0] = __float_as_uint(av[r0 * SM_PITCH + kk + qcol]);
                af[mt][1] = __float_as_uint(av[(r0 + 8) * SM_PITCH + kk + qcol]);
                af[mt][2] = __float_as_uint(av[r0 * SM_PITCH + kk + qcol + 4]);
                af[mt][3] = __float_as_uint(av[(r0 + 8) * SM_PITCH + kk + qcol + 4]);
            }
            #pragma unroll
            for (int nt = 0; nt < 4; nt++) {
                const int n0 = wc * 32 + nt * 8 + qrow;
                bf[nt][0] = __float_as_uint(bv[n0 * SM_PITCH + kk + qcol]);
                bf[nt][1] = __float_as_uint(bv[n0 * SM_PITCH + kk + qcol + 4]);
            }
            #pragma unroll
            for (int mt = 0; mt < 4; mt++)
                #pragma unroll
                for (int nt = 0; nt < 4; nt++)
                    mma_tf32(acc[mt][nt], af[mt], bf[nt]);
        }
    }

    __half* gout = gbd + ((size_t)bh << 20);
    const float* br = brv + h * QL;
    #pragma unroll
    for (int mt = 0; mt < 4; mt++) {
        const int row = row0 + wr * 64 + mt * 16 + qrow;
        #pragma unroll
        for (int nt = 0; nt < 4; nt++) {
            const int col = col0 + wc * 32 + nt * 8 + qcol * 2;
            *(__half2*)&gout[(size_t)row * 1024 + col] =
                __floats2half2_rn(acc[mt][nt][0] + br[col], acc[mt][nt][1] + br[col + 1]);
            *(__half2*)&gout[(size_t)(row + 8) * 1024 + col] =
                __floats2half2_rn(acc[mt][nt][2] + br[col], acc[mt][nt][3] + br[col + 1]);
        }
    }
}

// ---------------- bias precompute ----------------
__global__ __launch_bounds__(256) void bias_k_kernel(const float* __restrict__ heads,
                                                     const float* __restrict__ rwb,
                                                     float* __restrict__ bk) {
    int gt = blockIdx.x * 256 + threadIdx.x;
    int wi = gt >> 5, lane = gt & 31;
    int j = wi & (QL - 1);
    int bh = wi >> 10;
    int b = bh >> 4, h = bh & 15;
    const float* kp = heads + ((size_t)j * BS + b) * HCOLS + 1024 + h * 64;
    const float* wp = rwb + h * 64;
    float s = kp[lane] * wp[lane] + kp[lane + 32] * wp[lane + 32];
    #pragma unroll
    for (int o = 16; o; o >>= 1) s += __shfl_xor_sync(0xffffffffu, s, o);
    if (lane == 0) bk[wi] = s;
}
__global__ __launch_bounds__(256) void bias_r_kernel(const float* __restrict__ rk,
                                                     const float* __restrict__ rrb,
                                                     float* __restrict__ brv) {
    int gt = blockIdx.x * 256 + threadIdx.x;
    int wi = gt >> 5, lane = gt & 31;
    int m = wi & (QL - 1);
    int h = wi >> 10;
    const float* rp = rk + (size_t)m * DMODEL + h * 64;
    const float* wp = rrb + h * 64;
    float s = rp[lane] * wp[lane] + rp[lane + 32] * wp[lane + 32];
    #pragma unroll
    for (int o = 16; o; o >>= 1) s += __shfl_xor_sync(0xffffffffu, s, o);
    if (lane == 0) brv[wi] = s;
}

// ---------------- tensor-core flash attention ----------------
constexpr int QP = 68;
constexpr int VP = 72;
constexpr int ATTN2_FLOATS = 128 * QP + 64 * QP + 64 * VP + 128 * QP + 64;
constexpr int ATTN2_BYTES  = ATTN2_FLOATS * 4;

__global__ __launch_bounds__(256)
void attn2(const float* __restrict__ heads, const float* __restrict__ biask,
           const __half* __restrict__ gbd, float* __restrict__ vec) {
    extern __shared__ float sm[];
    float* q_s = sm;
    float* k_s = q_s + 128 * QP;
    float* v_s = k_s + 64 * QP;
    float* p_s = v_s + 64 * VP;
    float* bks = p_s + 128 * QP;

    const int bh = blockIdx.x, b = bh >> 4, h = bh & 15;
    const int ib = (int)gridDim.y - 1 - (int)blockIdx.y;
    const int i0 = ib * 128;
    const int t = threadIdx.x, wid = t >> 5, lane = t & 31;
    const int qr = lane >> 2, qc = lane & 3;
    const int rbase = wid * 16 + qr;

    #pragma unroll
    for (int i = 0; i < 8; i++) {
        int e = t + i * 256;
        int ii = e >> 4, d4 = (e & 15) * 4;
        *(float4*)&q_s[ii * QP + d4] =
            *(const float4*)&heads[((size_t)(i0 + ii) * BS + b) * HCOLS + h * 64 + d4];
    }

    float oacc[8][4] = {};
    float m_run[2] = {-1e30f, -1e30f}, l_run[2] = {0.f, 0.f};
    const float* bk = biask + (size_t)(b * NHEAD + h) * QL;
    const size_t gbase = (size_t)bh << 20;

    const int njt = 2 * ib + 2;
    for (int jt = 0; jt < njt; jt++) {
        const int j0 = jt * 64;
        __syncthreads();
        #pragma unroll
        for (int i = 0; i < 4; i++) {
            int e = t + i * 256;
            int jj = e >> 4, d4 = (e & 15) * 4;
            size_t base = ((size_t)(j0 + jj) * BS + b) * HCOLS + h * 64 + d4;
            *(float4*)&k_s[jj * QP + d4] = *(const float4*)&heads[base + 1024];
            *(float4*)&v_s[jj * VP + d4] = *(const float4*)&heads[base + 2048];
        }
        if (t < 64) bks[t] = bk[j0 + t];
        __syncthreads();

        float sacc[8][4] = {};
        #pragma unroll
        for (int ks = 0; ks < 8; ks++) {
            const int kk = ks * 8;
            uint32_t af[4];
            af[0] = __float_as_uint(q_s[rbase * QP + kk + qc]);
            af[1] = __float_as_uint(q_s[(rbase + 8) * QP + kk + qc]);
            af[2] = __float_as_uint(q_s[rbase * QP + kk + qc + 4]);
            af[3] = __float_as_uint(q_s[(rbase + 8) * QP + kk + qc + 4]);
            #pragma unroll
            for (int nt = 0; nt < 8; nt++) {
                uint32_t bf[2];
                bf[0] = __float_as_uint(k_s[(nt * 8 + qr) * QP + kk + qc]);
                bf[1] = __float_as_uint(k_s[(nt * 8 + qr) * QP + kk + qc + 4]);
                mma_tf32(sacc[nt], af, bf);
            }
        }

        #pragma unroll
        for (int s = 0; s < 2; s++) {
            const int ig = i0 + rbase + s * 8;
            const __half* grow = gbd + gbase + (size_t)ig * 1024 + (1023 - ig + j0);
            #pragma unroll
            for (int nt = 0; nt < 8; nt++) {
                #pragma unroll
                for (int r = 0; r < 2; r++) {
                    const int jl = nt * 8 + qc * 2 + r;
                    const int jg = j0 + jl;
                    float v = sacc[nt][s * 2 + r];
                    if (jg <= ig) v = (v + bks[jl] + __half2float(grow[jl])) * SCALE;
                    else          v = -1e30f;
                    sacc[nt][s * 2 + r] = v;
                }
            }
        }

        #pragma unroll
        for (int s = 0; s < 2; s++) {
            float mx = -1e30f;
            #pragma unroll
            for (int nt = 0; nt < 8; nt++)
                mx = fmaxf(mx, fmaxf(sacc[nt][s * 2], sacc[nt][s * 2 + 1]));
            mx = fmaxf(mx, __shfl_xor_sync(0xffffffffu, mx, 1));
            mx = fmaxf(mx, __shfl_xor_sync(0xffffffffu, mx, 2));
            float mnew = fmaxf(m_run[s], mx);
            float corr = __expf(m_run[s] - mnew);
            float rs = 0.f;
            #pragma unroll
            for (int nt = 0; nt < 8; nt++) {
                float p0 = __expf(sacc[nt][s * 2] - mnew);
                float p1 = __expf(sacc[nt][s * 2 + 1] - mnew);
                sacc[nt][s * 2] = p0; sacc[nt][s * 2 + 1] = p1;
                rs += p0 + p1;
            }
            rs += __shfl_xor_sync(0xffffffffu, rs, 1);
            rs += __shfl_xor_sync(0xffffffffu, rs, 2);
            l_run[s] = l_run[s] * corr + rs;
            m_run[s] = mnew;
            #pragma unroll
            for (int nt = 0; nt < 8; nt++) {
                oacc[nt][s * 2] *= corr;
                oacc[nt][s * 2 + 1] *= corr;
            }
        }

        #pragma unroll
        for (int s = 0; s < 2; s++) {
            #pragma unroll
            for (int nt = 0; nt < 8; nt++) {
                p_s[(rbase + s * 8) * QP + nt * 8 + qc * 2]     = tf32r(sacc[nt][s * 2]);
                p_s[(rbase + s * 8) * QP + nt * 8 + qc * 2 + 1] = tf32r(sacc[nt][s * 2 + 1]);
            }
        }
        __syncwarp();

        #pragma unroll
        for (int ks = 0; ks < 8; ks++) {
            uint32_t af[4];
            af[0] = __float_as_uint(p_s[rbase * QP + ks * 8 + qc]);
            af[1] = __float_as_uint(p_s[(rbase + 8) * QP + ks * 8 + qc]);
            af[2] = __float_as_uint(p_s[rbase * QP + ks * 8 + qc + 4]);
            af[3] = __float_as_uint(p_s[(rbase + 8) * QP + ks * 8 + qc + 4]);
            #pragma unroll
            for (int nt = 0; nt < 8; nt++) {
                uint32_t bf[2];
                bf[0] = __float_as_uint(v_s[(ks * 8 + qc) * VP + nt * 8 + qr]);
                bf[1] = __float_as_uint(v_s[(ks * 8 + qc + 4) * VP + nt * 8 + qr]);
                mma_tf32(oacc[nt], af, bf);
            }
        }
    }

    #pragma unroll
    for (int s = 0; s < 2; s++) {
        const int ig = i0 + rbase + s * 8;
        const float inv = 1.f / l_run[s];
        #pragma unroll
        for (int nt = 0; nt < 8; nt++) {
            float2 o2 = make_float2(oacc[nt][s * 2] * inv, oacc[nt][s * 2 + 1] * inv);
            *(float2*)&vec[((size_t)ig * BS + b) * DMODEL + h * 64 + nt * 8 + qc * 2] = o2;
        }
    }
}

// ---------------- residual + layernorm ----------------
__global__ __launch_bounds__(256) void ln_kernel(const float* __restrict__ w,
                                                 const float* __restrict__ proj,
                                                 const float* __restrict__ g,
                                                 const float* __restrict__ bta,
                                                 float* __restrict__ out) {
    __shared__ float red[8];
    const int row = blockIdx.x;
    const int t = threadIdx.x;
    const size_t base = (size_t)row * DMODEL;
    float x[4];
    float s = 0.f;
    #pragma unroll
    for (int u = 0; u < 4; u++) {
        int c = t + u * 256;
        x[u] = w[base + c] + proj[base + c];
        s += x[u];
    }
    #pragma unroll
    for (int o = 16; o; o >>= 1) s += __shfl_xor_sync(0xffffffffu, s, o);
    if ((t & 31) == 0) red[t >> 5] = s;
    __syncthreads();
    float tot = 0.f;
    #pragma unroll
    for (int i = 0; i < 8; i++) tot += red[i];
    const float mu = tot * (1.f / DMODEL);

    float vs = 0.f;
    #pragma unroll
    for (int u = 0; u < 4; u++) { float dd = x[u] - mu; vs += dd * dd; }
    #pragma unroll
    for (int o = 16; o; o >>= 1) vs += __shfl_xor_sync(0xffffffffu, vs, o);
    __syncthreads();
    if ((t & 31) == 0) red[t >> 5] = vs;
    __syncthreads();
    tot = 0.f;
    #pragma unroll
    for (int i = 0; i < 8; i++) tot += red[i];
    const float rstd = rsqrtf(tot * (1.f / DMODEL) + LNEPS);

    #pragma unroll
    for (int u = 0; u < 4; u++) {
        int c = t + u * 256;
        out[base + c] = (x[u] - mu) * rstd * g[c] + bta[c];
    }
}

// ---------------- launch ----------------
extern "C" void kernel_launch(void* const* d_in, const int* in_sizes, int n_in,
                              void* d_out, int out_size) {
    const float* w    = (const float*)d_in[0];
    const float* r    = (const float*)d_in[1];
    const float* qkvw = (const float*)d_in[3];
    const float* rw   = (const float*)d_in[4];
    const float* ow   = (const float*)d_in[5];
    const float* rrb  = (const float*)d_in[6];
    const float* rwb  = (const float*)d_in[7];
    const float* lng  = (const float*)d_in[8];
    const float* lnb  = (const float*)d_in[9];
    float* out = (float*)d_out;

    float *heads, *rkbuf, *bk, *brv, *vec, *proj;
    __half* gbd;
    cudaGetSymbolAddress((void**)&heads, g_heads);
    cudaGetSymbolAddress((void**)&rkbuf, g_rk);
    cudaGetSymbolAddress((void**)&bk,    g_biask);
    cudaGetSymbolAddress((void**)&brv,   g_biasr);
    cudaGetSymbolAddress((void**)&vec,   g_vec);
    cudaGetSymbolAddress((void**)&proj,  g_proj);
    cudaGetSymbolAddress((void**)&gbd,   g_bd);

    cudaFuncSetAttribute(attn2, cudaFuncAttributeMaxDynamicSharedMemorySize, ATTN2_BYTES);
    cudaFuncSetAttribute(gemm_tf32, cudaFuncAttributeMaxDynamicSharedMemorySize, GEMM_SMEM);
    cudaFuncSetAttribute(gemm_qkv_rk, cudaFuncAttributeMaxDynamicSharedMemorySize, GEMM_SMEM);
    cudaFuncSetAttribute(gemm_bd, cudaFuncAttributeMaxDynamicSharedMemorySize, BD_SMEM);

    // 1) fused: heads = w @ qkv_w  AND  r_k = r @ r_w  (raw A and B; outputs rounded)
    gemm_qkv_rk<<<dim3(24, 40), 256, GEMM_SMEM>>>(w, qkvw, heads, r, rw, rkbuf);

    // 2) biases
    bias_k_kernel<<<(BS * NHEAD * QL * 32) / 256, 256>>>(heads, rwb, bk);
    bias_r_kernel<<<(NHEAD * QL * 32) / 256, 256>>>(rkbuf, rrb, brv);

    // 3) BD band (fp16 output)
    gemm_bd<<<dim3(8, 8, 64), 256, BD_SMEM>>>(heads, rkbuf, brv, gbd);

    // 4) tensor-core flash attention
    attn2<<<dim3(BS * NHEAD, QL / 128), 256, ATTN2_BYTES>>>(heads, bk, gbd, vec);

    // 5) proj = vec @ o_w (raw A and B; output feeds LN)
    gemm_tf32<<<dim3(DMODEL / 128, NROWS / 128), 256, GEMM_SMEM>>>(
        vec, ow, proj, DMODEL, DMODEL, 0);

    // 6) out = LN(w + proj)
    ln_kernel<<<NROWS, 256>>>(w, proj, lng, lnb, out);
}

// round 16
// speedup vs baseline: 1.9152x; 1.0874x over previous
#include <cuda_runtime.h>
#include <cuda_fp16.h>
#include <cstdint>
#include <cstddef>

// ---------------- problem constants ----------------
constexpr int QL     = 1024;
constexpr int BS     = 4;
constexpr int DMODEL = 1024;
constexpr int NHEAD  = 16;
constexpr int NROWS  = QL * BS;           // 4096
constexpr int HCOLS  = 3 * NHEAD * 64;    // 3072
constexpr float SCALE = 0.125f;
constexpr float LNEPS = 1e-5f;

// ---------------- scratch ----------------
__device__ float  g_heads[(size_t)NROWS * HCOLS];
__device__ float  g_rk[(size_t)QL * DMODEL];
__device__ float  g_biask[BS * NHEAD * QL];
__device__ float  g_biasr[NHEAD * QL];
__device__ float  g_vec[(size_t)NROWS * DMODEL];
__device__ float  g_proj[(size_t)NROWS * DMODEL];
__device__ __half g_bd[(size_t)64 * 1024 * 1024];   // G[bh][i][m] band scores (fp16)

__device__ __forceinline__ float tf32r(float x) {
    float y;
    asm("cvt.rna.tf32.f32 %0, %1;" : "=f"(y) : "f"(x));
    return y;
}
__device__ __forceinline__ void mma_tf32(float* d, const uint32_t* a, const uint32_t* b) {
    asm volatile(
        "mma.sync.aligned.m16n8k8.row.col.f32.tf32.tf32.f32 "
        "{%0,%1,%2,%3}, {%4,%5,%6,%7}, {%8,%9}, {%0,%1,%2,%3};\n"
        : "+f"(d[0]), "+f"(d[1]), "+f"(d[2]), "+f"(d[3])
        : "r"(a[0]), "r"(a[1]), "r"(a[2]), "r"(a[3]), "r"(b[0]), "r"(b[1]));
}
__device__ __forceinline__ void mma_f16(float* d, const uint32_t* a, const uint32_t* b) {
    asm volatile(
        "mma.sync.aligned.m16n8k16.row.col.f32.f16.f16.f32 "
        "{%0,%1,%2,%3}, {%4,%5,%6,%7}, {%8,%9}, {%0,%1,%2,%3};\n"
        : "+f"(d[0]), "+f"(d[1]), "+f"(d[2]), "+f"(d[3])
        : "r"(a[0]), "r"(a[1]), "r"(a[2]), "r"(a[3]), "r"(b[0]), "r"(b[1]));
}
__device__ __forceinline__ void cp16(uint32_t saddr, const void* g) {
    asm volatile("cp.async.cg.shared.global [%0], [%1], 16;" :: "r"(saddr), "l"(g));
}
#define CP_COMMIT() asm volatile("cp.async.commit_group;" ::: "memory")
#define CP_WAIT1()  asm volatile("cp.async.wait_group 1;" ::: "memory")
#define CP_WAIT0()  asm volatile("cp.async.wait_group 0;" ::: "memory")

__device__ __forceinline__ uint32_t pack_h2(float a, float b) {
    __half2 h = __floats2half2_rn(a, b);
    return *(uint32_t*)&h;
}

// ---------------- 2-stage cp.async tf32 GEMM core: C = A[M,K] @ B[K,N] ----------------
constexpr int KC   = 32;
constexpr int AP   = 36;
constexpr int BP   = 136;
constexpr int ASTG = 128 * AP;
constexpr int BSTG = KC * BP;
constexpr int GEMM_SMEM = 2 * (ASTG + BSTG) * 4;   // 71680 bytes -> 2 CTAs/SM

__device__ __forceinline__ void gemm_core(const float* __restrict__ A,
                                          const float* __restrict__ B,
                                          float* __restrict__ C,
                                          int N, int K, int row0, int col0,
                                          int roundOut, float* smx) {
    float* a_s = smx;
    float* b_s = smx + 2 * ASTG;
    const uint32_t a_sb = (uint32_t)__cvta_generic_to_shared(a_s);
    const uint32_t b_sb = (uint32_t)__cvta_generic_to_shared(b_s);

    const int t = threadIdx.x;
    const int wid = t >> 5, lane = t & 31;
    const int wr = wid >> 2, wc = wid & 3;
    const int qrow = lane >> 2, qcol = lane & 3;
    const int lr = t >> 3;
    const int kq = (t & 7) * 4;

    float acc[4][4][4] = {};

    auto load_chunk = [&](int c, int s) {
        const int k0 = c * KC;
        #pragma unroll
        for (int i = 0; i < 4; i++) {
            const int r2 = lr + i * 32;
            cp16(a_sb + (uint32_t)(s * ASTG + r2 * AP + kq) * 4,
                 &A[(size_t)(row0 + r2) * K + k0 + kq]);
            const int c2 = t + i * 256;
            const int kr = c2 >> 5, nc = (c2 & 31) * 4;
            cp16(b_sb + (uint32_t)(s * BSTG + kr * BP + nc) * 4,
                 &B[(size_t)(k0 + kr) * N + col0 + nc]);
        }
        CP_COMMIT();
    };

    const int NC = K / KC;
    load_chunk(0, 0);

    for (int c = 0; c < NC; c++) {
        const int s = c & 1;
        if (c + 1 < NC) { load_chunk(c + 1, s ^ 1); CP_WAIT1(); }
        else            { CP_WAIT0(); }
        __syncthreads();

        const float* av = a_s + s * ASTG;
        const float* bv = b_s + s * BSTG;
        #pragma unroll
        for (int ks = 0; ks < KC / 8; ks++) {
            const int kk = ks * 8;
            uint32_t af[4][4], bf[4][2];
            #pragma unroll
            for (int mt = 0; mt < 4; mt++) {
                const int r0 = wr * 64 + mt * 16 + qrow;
                af[mt][0] = __float_as_uint(av[r0 * AP + kk + qcol]);
                af[mt][1] = __float_as_uint(av[(r0 + 8) * AP + kk + qcol]);
                af[mt][2] = __float_as_uint(av[r0 * AP + kk + qcol + 4]);
                af[mt][3] = __float_as_uint(av[(r0 + 8) * AP + kk + qcol + 4]);
            }
            #pragma unroll
            for (int nt = 0; nt < 4; nt++) {
                const int n0 = wc * 32 + nt * 8 + qrow;
                bf[nt][0] = __float_as_uint(bv[(kk + qcol) * BP + n0]);
                bf[nt][1] = __float_as_uint(bv[(kk + qcol + 4) * BP + n0]);
            }
            #pragma unroll
            for (int mt = 0; mt < 4; mt++)
                #pragma unroll
                for (int nt = 0; nt < 4; nt++)
                    mma_tf32(acc[mt][nt], af[mt], bf[nt]);
        }
        __syncthreads();
    }

    #pragma unroll
    for (int mt = 0; mt < 4; mt++) {
        const int row = row0 + wr * 64 + mt * 16 + qrow;
        #pragma unroll
        for (int nt = 0; nt < 4; nt++) {
            const int col = col0 + wc * 32 + nt * 8 + qcol * 2;
            float2 v0 = make_float2(acc[mt][nt][0], acc[mt][nt][1]);
            float2 v1 = make_float2(acc[mt][nt][2], acc[mt][nt][3]);
            if (roundOut) {
                v0.x = tf32r(v0.x); v0.y = tf32r(v0.y);
                v1.x = tf32r(v1.x); v1.y = tf32r(v1.y);
            }
            *(float2*)&C[(size_t)row * N + col] = v0;
            *(float2*)&C[(size_t)(row + 8) * N + col] = v1;
        }
    }
}

// generic wrapper (proj)
__global__ __launch_bounds__(256, 2)
void gemm_tf32(const float* __restrict__ A, const float* __restrict__ B,
               float* __restrict__ C, int N, int K, int roundOut) {
    extern __shared__ float smx[];
    gemm_core(A, B, C, N, K, blockIdx.y * 128, blockIdx.x * 128, roundOut, smx);
}

// fused qkv + rk launch: grid (24, 40); by<32 -> qkv tile, else rk tile
__global__ __launch_bounds__(256, 2)
void gemm_qkv_rk(const float* __restrict__ w, const float* __restrict__ qkvw,
                 float* __restrict__ heads,
                 const float* __restrict__ r, const float* __restrict__ rw,
                 float* __restrict__ rkbuf) {
    extern __shared__ float smx[];
    const float *A, *B; float* C; int N, K, row0, col0;
    if (blockIdx.y < 32) {
        A = w; B = qkvw; C = heads; N = HCOLS; K = DMODEL;
        row0 = blockIdx.y * 128; col0 = blockIdx.x * 128;
    } else {
        if (blockIdx.x >= 8) return;
        A = r; B = rw; C = rkbuf; N = DMODEL; K = DMODEL;
        row0 = (blockIdx.y - 32) * 128; col0 = blockIdx.x * 128;
    }
    gemm_core(A, B, C, N, K, row0, col0, 1, smx);
}

// ---------------- BD band GEMM: gbd[bh][i][m] = fp16(q_i.rk[m] + biasr[h][m]) ----------------
constexpr int SM_PITCH = 36;
constexpr int GSTG = 128 * SM_PITCH;
constexpr int BD_SMEM = 2 * 2 * GSTG * 4;   // 73728 bytes

__global__ __launch_bounds__(256, 2)
void gemm_bd(const float* __restrict__ heads, const float* __restrict__ rkb,
             const float* __restrict__ brv, __half* __restrict__ gbd) {
    const int It = blockIdx.y, Mt = blockIdx.x;
    if (It + Mt < 7) return;
    const int bh = blockIdx.z, b = bh >> 4, h = bh & 15;

    extern __shared__ float smx[];
    float* a_s = smx;
    float* b_s = smx + 2 * GSTG;
    const uint32_t a_sb = (uint32_t)__cvta_generic_to_shared(a_s);
    const uint32_t b_sb = (uint32_t)__cvta_generic_to_shared(b_s);

    const int t = threadIdx.x;
    const int wid = t >> 5, lane = t & 31;
    const int wr = wid >> 2, wc = wid & 3;
    const int qrow = lane >> 2, qcol = lane & 3;
    const int row0 = It * 128, col0 = Mt * 128;

    const int lr = t >> 3;
    const int kq = (t & 7) * 4;

    #pragma unroll
    for (int c = 0; c < 2; c++) {
        const int k0 = c * KC;
        #pragma unroll
        for (int i = 0; i < 4; i++) {
            const int r2 = lr + i * 32;
            const uint32_t soff = (uint32_t)(c * GSTG + r2 * SM_PITCH + kq) * 4;
            cp16(a_sb + soff,
                 &heads[((size_t)(row0 + r2) * BS + b) * HCOLS + h * 64 + k0 + kq]);
            cp16(b_sb + soff,
                 &rkb[(size_t)(col0 + r2) * DMODEL + h * 64 + k0 + kq]);
        }
        CP_COMMIT();
    }

    float acc[4][4][4] = {};

    #pragma unroll
    for (int c = 0; c < 2; c++) {
        if (c == 0) CP_WAIT1(); else CP_WAIT0();
        __syncthreads();
        const float* av = a_s + c * GSTG;
        const float* bv = b_s + c * GSTG;
        #pragma unroll
        for (int ks = 0; ks < KC / 8; ks++) {
            const int kk = ks * 8;
            uint32_t af[4][4], bf[4][2];
            #pragma unroll
            for (int mt = 0; mt < 4; mt++) {
                const int r0 = wr * 64 + mt * 16 + qrow;
                af[mt][0] = __float_as_uint(av[r0 * SM_PITCH + kk + qcol]);
                af[mt][1] = __float_as_uint(av[(r0 + 8) * SM_PITCH + kk + qcol]);
                af[mt][2] = __float_as_uint(av[r0 * SM_PITCH + kk + qcol + 4]);
                af[mt][3] = __float_as_uint(av[(r0 + 8) * SM_PITCH + kk + qcol + 4]);
            }
            #pragma unroll
            for (int nt = 0; nt < 4; nt++) {
                const int n0 = wc * 32 + nt * 8 + qrow;
                bf[nt][0] = __float_as_uint(bv[n0 * SM_PITCH + kk + qcol]);
                bf[nt][1] = __float_as_uint(bv[n0 * SM_PITCH + kk + qcol + 4]);
            }
            #pragma unroll
            for (int mt = 0; mt < 4; mt++)
                #pragma unroll
                for (int nt = 0; nt < 4; nt++)
                    mma_tf32(acc[mt][nt], af[mt], bf[nt]);
        }
    }

    __half* gout = gbd + ((size_t)bh << 20);
    const float* br = brv + h * QL;
    #pragma unroll
    for (int mt = 0; mt < 4; mt++) {
        const int row = row0 + wr * 64 + mt * 16 + qrow;
        #pragma unroll
        for (int nt = 0; nt < 4; nt++) {
            const int col = col0 + wc * 32 + nt * 8 + qcol * 2;
            *(__half2*)&gout[(size_t)row * 1024 + col] =
                __floats2half2_rn(acc[mt][nt][0] + br[col], acc[mt][nt][1] + br[col + 1]);
            *(__half2*)&gout[(size_t)(row + 8) * 1024 + col] =
                __floats2half2_rn(acc[mt][nt][2] + br[col], acc[mt][nt][3] + br[col + 1]);
        }
    }
}

// ---------------- bias precompute ----------------
__global__ __launch_bounds__(256) void bias_k_kernel(const float* __restrict__ heads,
                                                     const float* __restrict__ rwb,
                                                     float* __restrict__ bk) {
    int gt = blockIdx.x * 256 + threadIdx.x;
    int wi = gt >> 5, lane = gt & 31;
    int j = wi & (QL - 1);
    int bh = wi >> 10;
    int b = bh >> 4, h = bh & 15;
    const float* kp = heads + ((size_t)j * BS + b) * HCOLS + 1024 + h * 64;
    const float* wp = rwb + h * 64;
    float s = kp[lane] * wp[lane] + kp[lane + 32] * wp[lane + 32];
    #pragma unroll
    for (int o = 16; o; o >>= 1) s += __shfl_xor_sync(0xffffffffu, s, o);
    if (lane == 0) bk[wi] = s;
}
__global__ __launch_bounds__(256) void bias_r_kernel(const float* __restrict__ rk,
                                                     const float* __restrict__ rrb,
                                                     float* __restrict__ brv) {
    int gt = blockIdx.x * 256 + threadIdx.x;
    int wi = gt >> 5, lane = gt & 31;
    int m = wi & (QL - 1);
    int h = wi >> 10;
    const float* rp = rk + (size_t)m * DMODEL + h * 64;
    const float* wp = rrb + h * 64;
    float s = rp[lane] * wp[lane] + rp[lane + 32] * wp[lane + 32];
    #pragma unroll
    for (int o = 16; o; o >>= 1) s += __shfl_xor_sync(0xffffffffu, s, o);
    if (lane == 0) brv[wi] = s;
}

// ---------------- tensor-core flash attention (fp16 QK, tf32 PV) ----------------
constexpr int QPH = 72;                 // q_h/k_h pitch (halves); /2=36 words -> conflict-free
constexpr int PP  = 68;                 // p_s pitch (floats)
constexpr int VP  = 72;                 // v_s pitch (floats)
constexpr int ATTN2_BYTES = (128 * QPH + 64 * QPH) * 2 + (64 * VP + 128 * PP + 64) * 4;
// = 27648 + 18432 + 34816 + 256 = 81152 bytes -> 2 CTAs/SM

__global__ __launch_bounds__(256, 2)
void attn2(const float* __restrict__ heads, const float* __restrict__ biask,
           const __half* __restrict__ gbd, float* __restrict__ vec) {
    extern __shared__ float sm[];
    __half* q_h = (__half*)sm;                      // [128][QPH] halves
    __half* k_h = q_h + 128 * QPH;                  // [64][QPH] halves
    float*  v_s = (float*)(k_h + 64 * QPH);         // [64][VP]
    float*  p_s = v_s + 64 * VP;                    // [128][PP]
    float*  bks = p_s + 128 * PP;                   // [64]
    uint32_t* q4 = (uint32_t*)q_h;
    uint32_t* k4 = (uint32_t*)k_h;

    const int bh = blockIdx.x, b = bh >> 4, h = bh & 15;
    const int ib = (int)gridDim.y - 1 - (int)blockIdx.y;
    const int i0 = ib * 128;
    const int t = threadIdx.x, wid = t >> 5, lane = t & 31;
    const int qr = lane >> 2, qc = lane & 3;
    const int rbase = wid * 16 + qr;

    // Q tile: 128x64 -> fp16 (8 float4 per thread)
    #pragma unroll
    for (int i = 0; i < 8; i++) {
        int e = t + i * 256;
        int ii = e >> 4, d4 = (e & 15) * 4;
        float4 v = *(const float4*)&heads[((size_t)(i0 + ii) * BS + b) * HCOLS + h * 64 + d4];
        q4[(ii * QPH + d4) >> 1]       = pack_h2(v.x, v.y);
        q4[((ii * QPH + d4) >> 1) + 1] = pack_h2(v.z, v.w);
    }

    float oacc[8][4] = {};
    float m_run[2] = {-1e30f, -1e30f}, l_run[2] = {0.f, 0.f};
    const float* bk = biask + (size_t)(b * NHEAD + h) * QL;
    const size_t gbase = (size_t)bh << 20;

    const int njt = 2 * ib + 2;
    for (int jt = 0; jt < njt; jt++) {
        const int j0 = jt * 64;
        __syncthreads();
        #pragma unroll
        for (int i = 0; i < 4; i++) {
            int e = t + i * 256;
            int jj = e >> 4, d4 = (e & 15) * 4;
            size_t base = ((size_t)(j0 + jj) * BS + b) * HCOLS + h * 64 + d4;
            float4 kv = *(const float4*)&heads[base + 1024];
            k4[(jj * QPH + d4) >> 1]       = pack_h2(kv.x, kv.y);
            k4[((jj * QPH + d4) >> 1) + 1] = pack_h2(kv.z, kv.w);
            *(float4*)&v_s[jj * VP + d4] = *(const float4*)&heads[base + 2048];
        }
        if (t < 64) bks[t] = bk[j0 + t];
        __syncthreads();

        // ---- S = Q K^T (fp16, m16n8k16: 4 k-chunks) ----
        float sacc[8][4] = {};
        #pragma unroll
        for (int ks = 0; ks < 4; ks++) {
            uint32_t af[4];
            af[0] = q4[rbase * (QPH / 2) + ks * 8 + qc];
            af[1] = q4[(rbase + 8) * (QPH / 2) + ks * 8 + qc];
            af[2] = q4[rbase * (QPH / 2) + ks * 8 + qc + 4];
            af[3] = q4[(rbase + 8) * (QPH / 2) + ks * 8 + qc + 4];
            #pragma unroll
            for (int nt = 0; nt < 8; nt++) {
                uint32_t bf[2];
                bf[0] = k4[(nt * 8 + qr) * (QPH / 2) + ks * 8 + qc];
                bf[1] = k4[(nt * 8 + qr) * (QPH / 2) + ks * 8 + qc + 4];
                mma_f16(sacc[nt], af, bf);
            }
        }

        // ---- + biask + BD band, scale, causal mask ----
        #pragma unroll
        for (int s = 0; s < 2; s++) {
            const int ig = i0 + rbase + s * 8;
            const __half* grow = gbd + gbase + (size_t)ig * 1024 + (1023 - ig + j0);
            #pragma unroll
            for (int nt = 0; nt < 8; nt++) {
                #pragma unroll
                for (int r = 0; r < 2; r++) {
                    const int jl = nt * 8 + qc * 2 + r;
                    const int jg = j0 + jl;
                    float v = sacc[nt][s * 2 + r];
                    if (jg <= ig) v = (v + bks[jl] + __half2float(grow[jl])) * SCALE;
                    else          v = -1e30f;
                    sacc[nt][s * 2 + r] = v;
                }
            }
        }

        // ---- online softmax ----
        #pragma unroll
        for (int s = 0; s < 2; s++) {
            float mx = -1e30f;
            #pragma unroll
            for (int nt = 0; nt < 8; nt++)
                mx = fmaxf(mx, fmaxf(sacc[nt][s * 2], sacc[nt][s * 2 + 1]));
            mx = fmaxf(mx, __shfl_xor_sync(0xffffffffu, mx, 1));
            mx = fmaxf(mx, __shfl_xor_sync(0xffffffffu, mx, 2));
            float mnew = fmaxf(m_run[s], mx);
            float corr = __expf(m_run[s] - mnew);
            float rs = 0.f;
            #pragma unroll
            for (int nt = 0; nt < 8; nt++) {
                float p0 = __expf(sacc[nt][s * 2] - mnew);
                float p1 = __expf(sacc[nt][s * 2 + 1] - mnew);
                sacc[nt][s * 2] = p0; sacc[nt][s * 2 + 1] = p1;
                rs += p0 + p1;
            }
            rs += __shfl_xor_sync(0xffffffffu, rs, 1);
            rs += __shfl_xor_sync(0xffffffffu, rs, 2);
            l_run[s] = l_run[s] * corr + rs;
            m_run[s] = mnew;
            #pragma unroll
            for (int nt = 0; nt < 8; nt++) {
                oacc[nt][s * 2] *= corr;
                oacc[nt][s * 2 + 1] *= corr;
            }
        }

        // ---- P -> smem (tf32), then O += P V (tf32 mma) ----
        #pragma unroll
        for (int s = 0; s < 2; s++) {
            #pragma unroll
            for (int nt = 0; nt < 8; nt++) {
                p_s[(rbase + s * 8) * PP + nt * 8 + qc * 2]     = tf32r(sacc[nt][s * 2]);
                p_s[(rbase + s * 8) * PP + nt * 8 + qc * 2 + 1] = tf32r(sacc[nt][s * 2 + 1]);
            }
        }
        __syncwarp();

        #pragma unroll
        for (int ks = 0; ks < 8; ks++) {
            uint32_t af[4];
            af[0] = __float_as_uint(p_s[rbase * PP + ks * 8 + qc]);
            af[1] = __float_as_uint(p_s[(rbase + 8) * PP + ks * 8 + qc]);
            af[2] = __float_as_uint(p_s[rbase * PP + ks * 8 + qc + 4]);
            af[3] = __float_as_uint(p_s[(rbase + 8) * PP + ks * 8 + qc + 4]);
            #pragma unroll
            for (int nt = 0; nt < 8; nt++) {
                uint32_t bf[2];
                bf[0] = __float_as_uint(v_s[(ks * 8 + qc) * VP + nt * 8 + qr]);
                bf[1] = __float_as_uint(v_s[(ks * 8 + qc + 4) * VP + nt * 8 + qr]);
                mma_tf32(oacc[nt], af, bf);
            }
        }
    }

    #pragma unroll
    for (int s = 0; s < 2; s++) {
        const int ig = i0 + rbase + s * 8;
        const float inv = 1.f / l_run[s];
        #pragma unroll
        for (int nt = 0; nt < 8; nt++) {
            float2 o2 = make_float2(oacc[nt][s * 2] * inv, oacc[nt][s * 2 + 1] * inv);
            *(float2*)&vec[((size_t)ig * BS + b) * DMODEL + h * 64 + nt * 8 + qc * 2] = o2;
        }
    }
}

// ---------------- residual + layernorm ----------------
__global__ __launch_bounds__(256) void ln_kernel(const float* __restrict__ w,
                                                 const float* __restrict__ proj,
                                                 const float* __restrict__ g,
                                                 const float* __restrict__ bta,
                                                 float* __restrict__ out) {
    __shared__ float red[8];
    const int row = blockIdx.x;
    const int t = threadIdx.x;
    const size_t base = (size_t)row * DMODEL;
    float x[4];
    float s = 0.f;
    #pragma unroll
    for (int u = 0; u < 4; u++) {
        int c = t + u * 256;
        x[u] = w[base + c] + proj[base + c];
        s += x[u];
    }
    #pragma unroll
    for (int o = 16; o; o >>= 1) s += __shfl_xor_sync(0xffffffffu, s, o);
    if ((t & 31) == 0) red[t >> 5] = s;
    __syncthreads();
    float tot = 0.f;
    #pragma unroll
    for (int i = 0; i < 8; i++) tot += red[i];
    const float mu = tot * (1.f / DMODEL);

    float vs = 0.f;
    #pragma unroll
    for (int u = 0; u < 4; u++) { float dd = x[u] - mu; vs += dd * dd; }
    #pragma unroll
    for (int o = 16; o; o >>= 1) vs += __shfl_xor_sync(0xffffffffu, vs, o);
    __syncthreads();
    if ((t & 31) == 0) red[t >> 5] = vs;
    __syncthreads();
    tot = 0.f;
    #pragma unroll
    for (int i = 0; i < 8; i++) tot += red[i];
    const float rstd = rsqrtf(tot * (1.f / DMODEL) + LNEPS);

    #pragma unroll
    for (int u = 0; u < 4; u++) {
        int c = t + u * 256;
        out[base + c] = (x[u] - mu) * rstd * g[c] + bta[c];
    }
}

// ---------------- launch ----------------
extern "C" void kernel_launch(void* const* d_in, const int* in_sizes, int n_in,
                              void* d_out, int out_size) {
    const float* w    = (const float*)d_in[0];
    const float* r    = (const float*)d_in[1];
    const float* qkvw = (const float*)d_in[3];
    const float* rw   = (const float*)d_in[4];
    const float* ow   = (const float*)d_in[5];
    const float* rrb  = (const float*)d_in[6];
    const float* rwb  = (const float*)d_in[7];
    const float* lng  = (const float*)d_in[8];
    const float* lnb  = (const float*)d_in[9];
    float* out = (float*)d_out;

    float *heads, *rkbuf, *bk, *brv, *vec, *proj;
    __half* gbd;
    cudaGetSymbolAddress((void**)&heads, g_heads);
    cudaGetSymbolAddress((void**)&rkbuf, g_rk);
    cudaGetSymbolAddress((void**)&bk,    g_biask);
    cudaGetSymbolAddress((void**)&brv,   g_biasr);
    cudaGetSymbolAddress((void**)&vec,   g_vec);
    cudaGetSymbolAddress((void**)&proj,  g_proj);
    cudaGetSymbolAddress((void**)&gbd,   g_bd);

    cudaFuncSetAttribute(attn2, cudaFuncAttributeMaxDynamicSharedMemorySize, ATTN2_BYTES);
    cudaFuncSetAttribute(gemm_tf32, cudaFuncAttributeMaxDynamicSharedMemorySize, GEMM_SMEM);
    cudaFuncSetAttribute(gemm_qkv_rk, cudaFuncAttributeMaxDynamicSharedMemorySize, GEMM_SMEM);
    cudaFuncSetAttribute(gemm_bd, cudaFuncAttributeMaxDynamicSharedMemorySize, BD_SMEM);

    // 1) fused: heads = w @ qkv_w  AND  r_k = r @ r_w
    gemm_qkv_rk<<<dim3(24, 40), 256, GEMM_SMEM>>>(w, qkvw, heads, r, rw, rkbuf);

    // 2) biases
    bias_k_kernel<<<(BS * NHEAD * QL * 32) / 256, 256>>>(heads, rwb, bk);
    bias_r_kernel<<<(NHEAD * QL * 32) / 256, 256>>>(rkbuf, rrb, brv);

    // 3) BD band (fp16 output, 2 CTAs/SM pinned)
    gemm_bd<<<dim3(8, 8, 64), 256, BD_SMEM>>>(heads, rkbuf, brv, gbd);

    // 4) flash attention (fp16 QK, tf32 PV)
    attn2<<<dim3(BS * NHEAD, QL / 128), 256, ATTN2_BYTES>>>(heads, bk, gbd, vec);

    // 5) proj = vec @ o_w
    gemm_tf32<<<dim3(DMODEL / 128, NROWS / 128), 256, GEMM_SMEM>>>(
        vec, ow, proj, DMODEL, DMODEL, 0);

    // 6) out = LN(w + proj)
    ln_kernel<<<NROWS, 256>>>(w, proj, lng, lnb, out);
}

// round 17
// speedup vs baseline: 2.5807x; 1.3475x over previous
#include <cuda_runtime.h>
#include <cuda_fp16.h>
#include <cstdint>
#include <cstddef>

// ---------------- problem constants ----------------
constexpr int QL     = 1024;
constexpr int BS     = 4;
constexpr int DMODEL = 1024;
constexpr int NHEAD  = 16;
constexpr int NROWS  = QL * BS;           // 4096
constexpr int HCOLS  = 3 * NHEAD * 64;    // 3072
constexpr float SCALE = 0.125f;
constexpr float LNEPS = 1e-5f;

// ---------------- scratch ----------------
__device__ __half g_headsH[(size_t)NROWS * 2048];   // q|k planes, fp16
__device__ float  g_headsV[(size_t)NROWS * DMODEL]; // v plane, f32
__device__ __half g_rkH[(size_t)QL * DMODEL];
__device__ float  g_biask[BS * NHEAD * QL];
__device__ float  g_biasr[NHEAD * QL];
__device__ __half g_vecH[(size_t)NROWS * DMODEL];
__device__ float  g_proj[(size_t)NROWS * DMODEL];
__device__ __half g_bd[(size_t)64 * 1024 * 1024];   // band scores (fp16)
__device__ __half g_wh[(size_t)NROWS * DMODEL];
__device__ __half g_rh[(size_t)QL * DMODEL];
__device__ __half g_qkvT[(size_t)HCOLS * DMODEL];   // qkv_w^T fp16 [N][K]
__device__ __half g_rwT[(size_t)DMODEL * DMODEL];
__device__ __half g_owT[(size_t)DMODEL * DMODEL];

__device__ __forceinline__ float tf32r(float x) {
    float y;
    asm("cvt.rna.tf32.f32 %0, %1;" : "=f"(y) : "f"(x));
    return y;
}
__device__ __forceinline__ void mma_tf32(float* d, const uint32_t* a, const uint32_t* b) {
    asm volatile(
        "mma.sync.aligned.m16n8k8.row.col.f32.tf32.tf32.f32 "
        "{%0,%1,%2,%3}, {%4,%5,%6,%7}, {%8,%9}, {%0,%1,%2,%3};\n"
        : "+f"(d[0]), "+f"(d[1]), "+f"(d[2]), "+f"(d[3])
        : "r"(a[0]), "r"(a[1]), "r"(a[2]), "r"(a[3]), "r"(b[0]), "r"(b[1]));
}
__device__ __forceinline__ void mma_f16(float* d, const uint32_t* a, const uint32_t* b) {
    asm volatile(
        "mma.sync.aligned.m16n8k16.row.col.f32.f16.f16.f32 "
        "{%0,%1,%2,%3}, {%4,%5,%6,%7}, {%8,%9}, {%0,%1,%2,%3};\n"
        : "+f"(d[0]), "+f"(d[1]), "+f"(d[2]), "+f"(d[3])
        : "r"(a[0]), "r"(a[1]), "r"(a[2]), "r"(a[3]), "r"(b[0]), "r"(b[1]));
}
__device__ __forceinline__ void cp16(uint32_t saddr, const void* g) {
    asm volatile("cp.async.cg.shared.global [%0], [%1], 16;" :: "r"(saddr), "l"(g));
}
#define CP_COMMIT() asm volatile("cp.async.commit_group;" ::: "memory")
#define CP_WAIT1()  asm volatile("cp.async.wait_group 1;" ::: "memory")
#define CP_WAIT0()  asm volatile("cp.async.wait_group 0;" ::: "memory")

// ---------------- conversions ----------------
// w,r f32 -> fp16 flat (fused)
__global__ __launch_bounds__(256) void conv_wr(const float4* __restrict__ w,
                                               __half2* __restrict__ wh, int n4w,
                                               const float4* __restrict__ r,
                                               __half2* __restrict__ rh, int n4r) {
    int i = blockIdx.x * 256 + threadIdx.x;
    if (i < n4w) {
        float4 v = w[i];
        wh[i * 2]     = __floats2half2_rn(v.x, v.y);
        wh[i * 2 + 1] = __floats2half2_rn(v.z, v.w);
    } else {
        int j = i - n4w;
        if (j < n4r) {
            float4 v = r[j];
            rh[j * 2]     = __floats2half2_rn(v.x, v.y);
            rh[j * 2 + 1] = __floats2half2_rn(v.z, v.w);
        }
    }
}
// weight transpose + convert: out[n][k] = fp16(in[k][n])
__global__ __launch_bounds__(256) void convT(const float* __restrict__ in,
                                             __half* __restrict__ out,
                                             int K, int N) {
    __shared__ float t[32][33];
    int n0 = blockIdx.x * 32, k0 = blockIdx.y * 32;
    int tx = threadIdx.x, ty = threadIdx.y;
    #pragma unroll
    for (int i = 0; i < 32; i += 8)
        t[ty + i][tx] = in[(size_t)(k0 + ty + i) * N + n0 + tx];
    __syncthreads();
    #pragma unroll
    for (int i = 0; i < 32; i += 8)
        out[(size_t)(n0 + ty + i) * K + k0 + tx] = __float2half(t[tx][ty + i]);
}

// ---------------- fp16 GEMM core: C = A[M,K] @ B[N,K]^T, f32 acc ----------------
// KC=64 halves/chunk, pitch 72 halves, 2-stage cp.async, m16n8k16.
constexpr int KCH   = 64;
constexpr int PH    = 72;                 // halves; /2 = 36 words, conflict-free frags
constexpr int STGH  = 128 * PH;           // halves per stage per operand
constexpr int GEMMH_SMEM = 2 * 2 * STGH * 2;   // 73728 bytes -> 2 CTAs/SM
constexpr int BDH_SMEM   = 2 * STGH * 2;       // 36864 bytes

__device__ __forceinline__ void gemm_f16_core(const __half* __restrict__ A,
                                              const __half* __restrict__ B,
                                              float* Cf, __half* Ch,
                                              int outN, int K,
                                              int row0, int col0, int outcol0,
                                              char* smraw) {
    __half* a_h = (__half*)smraw;          // [2][STGH]
    __half* b_h = a_h + 2 * STGH;
    const uint32_t a_sb = (uint32_t)__cvta_generic_to_shared(a_h);
    const uint32_t b_sb = (uint32_t)__cvta_generic_to_shared(b_h);

    const int t = threadIdx.x;
    const int wid = t >> 5, lane = t & 31;
    const int wr = wid >> 2, wc = wid & 3;
    const int qrow = lane >> 2, qcol = lane & 3;

    float acc[4][4][4] = {};

    auto load_chunk = [&](int c, int s) {
        const int k0 = c * KCH;
        #pragma unroll
        for (int i = 0; i < 4; i++) {
            const int idx = t + i * 256;
            const int row = idx >> 3, h8 = (idx & 7) * 8;
            cp16(a_sb + (uint32_t)(s * STGH + row * PH + h8) * 2,
                 &A[(size_t)(row0 + row) * K + k0 + h8]);
            cp16(b_sb + (uint32_t)(s * STGH + row * PH + h8) * 2,
                 &B[(size_t)(col0 + row) * K + k0 + h8]);
        }
        CP_COMMIT();
    };

    const int NC = K / KCH;
    load_chunk(0, 0);

    for (int c = 0; c < NC; c++) {
        const int s = c & 1;
        if (c + 1 < NC) { load_chunk(c + 1, s ^ 1); CP_WAIT1(); }
        else            { CP_WAIT0(); }
        __syncthreads();

        const uint32_t* a4 = (const uint32_t*)(a_h + s * STGH);
        const uint32_t* b4 = (const uint32_t*)(b_h + s * STGH);
        #pragma unroll
        for (int ks = 0; ks < 4; ks++) {
            uint32_t af[4][4], bf[4][2];
            #pragma unroll
            for (int mt = 0; mt < 4; mt++) {
                const int r0 = wr * 64 + mt * 16 + qrow;
                af[mt][0] = a4[r0 * (PH / 2) + ks * 8 + qcol];
                af[mt][1] = a4[(r0 + 8) * (PH / 2) + ks * 8 + qcol];
                af[mt][2] = a4[r0 * (PH / 2) + ks * 8 + qcol + 4];
                af[mt][3] = a4[(r0 + 8) * (PH / 2) + ks * 8 + qcol + 4];
            }
            #pragma unroll
            for (int nt = 0; nt < 4; nt++) {
                const int n0 = wc * 32 + nt * 8 + qrow;
                bf[nt][0] = b4[n0 * (PH / 2) + ks * 8 + qcol];
                bf[nt][1] = b4[n0 * (PH / 2) + ks * 8 + qcol + 4];
            }
            #pragma unroll
            for (int mt = 0; mt < 4; mt++)
                #pragma unroll
                for (int nt = 0; nt < 4; nt++)
                    mma_f16(acc[mt][nt], af[mt], bf[nt]);
        }
        __syncthreads();
    }

    #pragma unroll
    for (int mt = 0; mt < 4; mt++) {
        const int row = row0 + wr * 64 + mt * 16 + qrow;
        #pragma unroll
        for (int nt = 0; nt < 4; nt++) {
            const int col = outcol0 + wc * 32 + nt * 8 + qcol * 2;
            if (Cf) {
                *(float2*)&Cf[(size_t)row * outN + col] =
                    make_float2(acc[mt][nt][0], acc[mt][nt][1]);
                *(float2*)&Cf[(size_t)(row + 8) * outN + col] =
                    make_float2(acc[mt][nt][2], acc[mt][nt][3]);
            } else {
                *(__half2*)&Ch[(size_t)row * outN + col] =
                    __floats2half2_rn(acc[mt][nt][0], acc[mt][nt][1]);
                *(__half2*)&Ch[(size_t)(row + 8) * outN + col] =
                    __floats2half2_rn(acc[mt][nt][2], acc[mt][nt][3]);
            }
        }
    }
}

// proj: f32 out
__global__ __launch_bounds__(256, 2)
void gemm_f16(const __half* __restrict__ A, const __half* __restrict__ B,
              float* __restrict__ C, int N, int K) {
    extern __shared__ char smraw[];
    gemm_f16_core(A, B, C, nullptr, N, K, blockIdx.y * 128, blockIdx.x * 128,
                  blockIdx.x * 128, smraw);
}

// fused qkv + rk: grid (24, 40). qkv q|k cols -> fp16 headsH, v cols -> f32 headsV.
__global__ __launch_bounds__(256, 2)
void gemm_qkv_rk(const __half* __restrict__ wh, const __half* __restrict__ qkvT,
                 __half* __restrict__ headsH, float* __restrict__ headsV,
                 const __half* __restrict__ rh, const __half* __restrict__ rwT,
                 __half* __restrict__ rkH) {
    extern __shared__ char smraw[];
    if (blockIdx.y < 32) {
        const int col0 = blockIdx.x * 128;
        if (col0 < 2048)
            gemm_f16_core(wh, qkvT, nullptr, headsH, 2048, DMODEL,
                          blockIdx.y * 128, col0, col0, smraw);
        else
            gemm_f16_core(wh, qkvT, headsV, nullptr, 1024, DMODEL,
                          blockIdx.y * 128, col0, col0 - 2048, smraw);
    } else {
        if (blockIdx.x >= 8) return;
        gemm_f16_core(rh, rwT, nullptr, rkH, 1024, DMODEL,
                      (blockIdx.y - 32) * 128, blockIdx.x * 128,
                      blockIdx.x * 128, smraw);
    }
}

// ---------------- BD band GEMM (fp16, single K=64 chunk) ----------------
__global__ __launch_bounds__(256, 2)
void gemm_bd(const __half* __restrict__ headsH, const __half* __restrict__ rkH,
             const float* __restrict__ brv, __half* __restrict__ gbd) {
    const int It = blockIdx.y, Mt = blockIdx.x;
    if (It + Mt < 7) return;
    const int bh = blockIdx.z, b = bh >> 4, h = bh & 15;

    extern __shared__ char smraw[];
    __half* a_h = (__half*)smraw;          // [128][PH]
    __half* b_h = a_h + STGH;
    const uint32_t a_sb = (uint32_t)__cvta_generic_to_shared(a_h);
    const uint32_t b_sb = (uint32_t)__cvta_generic_to_shared(b_h);

    const int t = threadIdx.x;
    const int wid = t >> 5, lane = t & 31;
    const int wr = wid >> 2, wc = wid & 3;
    const int qrow = lane >> 2, qcol = lane & 3;
    const int row0 = It * 128, col0 = Mt * 128;

    #pragma unroll
    for (int i = 0; i < 4; i++) {
        const int idx = t + i * 256;
        const int row = idx >> 3, h8 = (idx & 7) * 8;
        cp16(a_sb + (uint32_t)(row * PH + h8) * 2,
             &headsH[((size_t)(row0 + row) * BS + b) * 2048 + h * 64 + h8]);
        cp16(b_sb + (uint32_t)(row * PH + h8) * 2,
             &rkH[(size_t)(col0 + row) * 1024 + h * 64 + h8]);
    }
    CP_COMMIT();
    CP_WAIT0();
    __syncthreads();

    float acc[4][4][4] = {};
    const uint32_t* a4 = (const uint32_t*)a_h;
    const uint32_t* b4 = (const uint32_t*)b_h;
    #pragma unroll
    for (int ks = 0; ks < 4; ks++) {
        uint32_t af[4][4], bf[4][2];
        #pragma unroll
        for (int mt = 0; mt < 4; mt++) {
            const int r0 = wr * 64 + mt * 16 + qrow;
            af[mt][0] = a4[r0 * (PH / 2) + ks * 8 + qcol];
            af[mt][1] = a4[(r0 + 8) * (PH / 2) + ks * 8 + qcol];
            af[mt][2] = a4[r0 * (PH / 2) + ks * 8 + qcol + 4];
            af[mt][3] = a4[(r0 + 8) * (PH / 2) + ks * 8 + qcol + 4];
        }
        #pragma unroll
        for (int nt = 0; nt < 4; nt++) {
            const int n0 = wc * 32 + nt * 8 + qrow;
            bf[nt][0] = b4[n0 * (PH / 2) + ks * 8 + qcol];
            bf[nt][1] = b4[n0 * (PH / 2) + ks * 8 + qcol + 4];
        }
        #pragma unroll
        for (int mt = 0; mt < 4; mt++)
            #pragma unroll
            for (int nt = 0; nt < 4; nt++)
                mma_f16(acc[mt][nt], af[mt], bf[nt]);
    }

    __half* gout = gbd + ((size_t)bh << 20);
    const float* br = brv + h * QL;
    #pragma unroll
    for (int mt = 0; mt < 4; mt++) {
        const int row = row0 + wr * 64 + mt * 16 + qrow;
        #pragma unroll
        for (int nt = 0; nt < 4; nt++) {
            const int col = col0 + wc * 32 + nt * 8 + qcol * 2;
            *(__half2*)&gout[(size_t)row * 1024 + col] =
                __floats2half2_rn(acc[mt][nt][0] + br[col], acc[mt][nt][1] + br[col + 1]);
            *(__half2*)&gout[(size_t)(row + 8) * 1024 + col] =
                __floats2half2_rn(acc[mt][nt][2] + br[col], acc[mt][nt][3] + br[col + 1]);
        }
    }
}

// ---------------- bias precompute (fp16 inputs) ----------------
__global__ __launch_bounds__(256) void bias_k_kernel(const __half* __restrict__ headsH,
                                                     const float* __restrict__ rwb,
                                                     float* __restrict__ bk) {
    int gt = blockIdx.x * 256 + threadIdx.x;
    int wi = gt >> 5, lane = gt & 31;
    int j = wi & (QL - 1);
    int bh = wi >> 10;
    int b = bh >> 4, h = bh & 15;
    const __half* kp = headsH + ((size_t)j * BS + b) * 2048 + 1024 + h * 64;
    const float* wp = rwb + h * 64;
    float s = __half2float(kp[lane]) * wp[lane] +
              __half2float(kp[lane + 32]) * wp[lane + 32];
    #pragma unroll
    for (int o = 16; o; o >>= 1) s += __shfl_xor_sync(0xffffffffu, s, o);
    if (lane == 0) bk[wi] = s;
}
__global__ __launch_bounds__(256) void bias_r_kernel(const __half* __restrict__ rkH,
                                                     const float* __restrict__ rrb,
                                                     float* __restrict__ brv) {
    int gt = blockIdx.x * 256 + threadIdx.x;
    int wi = gt >> 5, lane = gt & 31;
    int m = wi & (QL - 1);
    int h = wi >> 10;
    const __half* rp = rkH + (size_t)m * DMODEL + h * 64;
    const float* wp = rrb + h * 64;
    float s = __half2float(rp[lane]) * wp[lane] +
              __half2float(rp[lane + 32]) * wp[lane + 32];
    #pragma unroll
    for (int o = 16; o; o >>= 1) s += __shfl_xor_sync(0xffffffffu, s, o);
    if (lane == 0) brv[wi] = s;
}

// ---------------- tensor-core flash attention (fp16 QK, tf32 PV, fp16 vec out) ----------------
constexpr int QPH = 72;
constexpr int PP  = 68;
constexpr int VP  = 72;
constexpr int ATTN2_BYTES = (128 * QPH + 64 * QPH) * 2 + (64 * VP + 128 * PP + 64) * 4;
// 81152 bytes -> 2 CTAs/SM

__global__ __launch_bounds__(256, 2)
void attn2(const __half* __restrict__ headsH, const float* __restrict__ headsV,
           const float* __restrict__ biask, const __half* __restrict__ gbd,
           __half* __restrict__ vecH) {
    extern __shared__ float sm[];
    __half* q_h = (__half*)sm;
    __half* k_h = q_h + 128 * QPH;
    float*  v_s = (float*)(k_h + 64 * QPH);
    float*  p_s = v_s + 64 * VP;
    float*  bks = p_s + 128 * PP;
    uint32_t* q4 = (uint32_t*)q_h;
    uint32_t* k4 = (uint32_t*)k_h;

    const int bh = blockIdx.x, b = bh >> 4, h = bh & 15;
    const int ib = (int)gridDim.y - 1 - (int)blockIdx.y;
    const int i0 = ib * 128;
    const int t = threadIdx.x, wid = t >> 5, lane = t & 31;
    const int qr = lane >> 2, qc = lane & 3;
    const int rbase = wid * 16 + qr;

    // Q tile: 128x64 halves (16B copies)
    #pragma unroll
    for (int i = 0; i < 4; i++) {
        int e = t + i * 256;
        int ii = e >> 3, d8 = (e & 7) * 8;
        *(uint4*)&q_h[ii * QPH + d8] =
            *(const uint4*)&headsH[((size_t)(i0 + ii) * BS + b) * 2048 + h * 64 + d8];
    }

    float oacc[8][4] = {};
    float m_run[2] = {-1e30f, -1e30f}, l_run[2] = {0.f, 0.f};
    const float* bk = biask + (size_t)(b * NHEAD + h) * QL;
    const size_t gbase = (size_t)bh << 20;

    const int njt = 2 * ib + 2;
    for (int jt = 0; jt < njt; jt++) {
        const int j0 = jt * 64;
        __syncthreads();
        #pragma unroll
        for (int i = 0; i < 2; i++) {      // K: 64x64 halves
            int e = t + i * 256;
            int jj = e >> 3, d8 = (e & 7) * 8;
            *(uint4*)&k_h[jj * QPH + d8] =
                *(const uint4*)&headsH[((size_t)(j0 + jj) * BS + b) * 2048 + 1024 + h * 64 + d8];
        }
        #pragma unroll
        for (int i = 0; i < 4; i++) {      // V: 64x64 floats
            int e = t + i * 256;
            int jj = e >> 4, d4 = (e & 15) * 4;
            *(float4*)&v_s[jj * VP + d4] =
                *(const float4*)&headsV[((size_t)(j0 + jj) * BS + b) * DMODEL + h * 64 + d4];
        }
        if (t < 64) bks[t] = bk[j0 + t];
        __syncthreads();

        // ---- S = Q K^T (fp16) ----
        float sacc[8][4] = {};
        #pragma unroll
        for (int ks = 0; ks < 4; ks++) {
            uint32_t af[4];
            af[0] = q4[rbase * (QPH / 2) + ks * 8 + qc];
            af[1] = q4[(rbase + 8) * (QPH / 2) + ks * 8 + qc];
            af[2] = q4[rbase * (QPH / 2) + ks * 8 + qc + 4];
            af[3] = q4[(rbase + 8) * (QPH / 2) + ks * 8 + qc + 4];
            #pragma unroll
            for (int nt = 0; nt < 8; nt++) {
                uint32_t bf[2];
                bf[0] = k4[(nt * 8 + qr) * (QPH / 2) + ks * 8 + qc];
                bf[1] = k4[(nt * 8 + qr) * (QPH / 2) + ks * 8 + qc + 4];
                mma_f16(sacc[nt], af, bf);
            }
        }

        // ---- + biask + BD band, scale, causal mask ----
        #pragma unroll
        for (int s = 0; s < 2; s++) {
            const int ig = i0 + rbase + s * 8;
            const __half* grow = gbd + gbase + (size_t)ig * 1024 + (1023 - ig + j0);
            #pragma unroll
            for (int nt = 0; nt < 8; nt++) {
                #pragma unroll
                for (int r = 0; r < 2; r++) {
                    const int jl = nt * 8 + qc * 2 + r;
                    const int jg = j0 + jl;
                    float v = sacc[nt][s * 2 + r];
                    if (jg <= ig) v = (v + bks[jl] + __half2float(grow[jl])) * SCALE;
                    else          v = -1e30f;
                    sacc[nt][s * 2 + r] = v;
                }
            }
        }

        // ---- online softmax ----
        #pragma unroll
        for (int s = 0; s < 2; s++) {
            float mx = -1e30f;
            #pragma unroll
            for (int nt = 0; nt < 8; nt++)
                mx = fmaxf(mx, fmaxf(sacc[nt][s * 2], sacc[nt][s * 2 + 1]));
            mx = fmaxf(mx, __shfl_xor_sync(0xffffffffu, mx, 1));
            mx = fmaxf(mx, __shfl_xor_sync(0xffffffffu, mx, 2));
            float mnew = fmaxf(m_run[s], mx);
            float corr = __expf(m_run[s] - mnew);
            float rs = 0.f;
            #pragma unroll
            for (int nt = 0; nt < 8; nt++) {
                float p0 = __expf(sacc[nt][s * 2] - mnew);
                float p1 = __expf(sacc[nt][s * 2 + 1] - mnew);
                sacc[nt][s * 2] = p0; sacc[nt][s * 2 + 1] = p1;
                rs += p0 + p1;
            }
            rs += __shfl_xor_sync(0xffffffffu, rs, 1);
            rs += __shfl_xor_sync(0xffffffffu, rs, 2);
            l_run[s] = l_run[s] * corr + rs;
            m_run[s] = mnew;
            #pragma unroll
            for (int nt = 0; nt < 8; nt++) {
                oacc[nt][s * 2] *= corr;
                oacc[nt][s * 2 + 1] *= corr;
            }
        }

        // ---- P -> smem (tf32), then O += P V (tf32 mma) ----
        #pragma unroll
        for (int s = 0; s < 2; s++) {
            #pragma unroll
            for (int nt = 0; nt < 8; nt++) {
                p_s[(rbase + s * 8) * PP + nt * 8 + qc * 2]     = tf32r(sacc[nt][s * 2]);
                p_s[(rbase + s * 8) * PP + nt * 8 + qc * 2 + 1] = tf32r(sacc[nt][s * 2 + 1]);
            }
        }
        __syncwarp();

        #pragma unroll
        for (int ks = 0; ks < 8; ks++) {
            uint32_t af[4];
            af[0] = __float_as_uint(p_s[rbase * PP + ks * 8 + qc]);
            af[1] = __float_as_uint(p_s[(rbase + 8) * PP + ks * 8 + qc]);
            af[2] = __float_as_uint(p_s[rbase * PP + ks * 8 + qc + 4]);
            af[3] = __float_as_uint(p_s[(rbase + 8) * PP + ks * 8 + qc + 4]);
            #pragma unroll
            for (int nt = 0; nt < 8; nt++) {
                uint32_t bf[2];
                bf[0] = __float_as_uint(v_s[(ks * 8 + qc) * VP + nt * 8 + qr]);
                bf[1] = __float_as_uint(v_s[(ks * 8 + qc + 4) * VP + nt * 8 + qr]);
                mma_tf32(oacc[nt], af, bf);
            }
        }
    }

    #pragma unroll
    for (int s = 0; s < 2; s++) {
        const int ig = i0 + rbase + s * 8;
        const float inv = 1.f / l_run[s];
        #pragma unroll
        for (int nt = 0; nt < 8; nt++) {
            *(__half2*)&vecH[((size_t)ig * BS + b) * DMODEL + h * 64 + nt * 8 + qc * 2] =
                __floats2half2_rn(oacc[nt][s * 2] * inv, oacc[nt][s * 2 + 1] * inv);
        }
    }
}

// ---------------- residual + layernorm ----------------
__global__ __launch_bounds__(256) void ln_kernel(const float* __restrict__ w,
                                                 const float* __restrict__ proj,
                                                 const float* __restrict__ g,
                                                 const float* __restrict__ bta,
                                                 float* __restrict__ out) {
    __shared__ float red[8];
    const int row = blockIdx.x;
    const int t = threadIdx.x;
    const size_t base = (size_t)row * DMODEL;
    float x[4];
    float s = 0.f;
    #pragma unroll
    for (int u = 0; u < 4; u++) {
        int c = t + u * 256;
        x[u] = w[base + c] + proj[base + c];
        s += x[u];
    }
    #pragma unroll
    for (int o = 16; o; o >>= 1) s += __shfl_xor_sync(0xffffffffu, s, o);
    if ((t & 31) == 0) red[t >> 5] = s;
    __syncthreads();
    float tot = 0.f;
    #pragma unroll
    for (int i = 0; i < 8; i++) tot += red[i];
    const float mu = tot * (1.f / DMODEL);

    float vs = 0.f;
    #pragma unroll
    for (int u = 0; u < 4; u++) { float dd = x[u] - mu; vs += dd * dd; }
    #pragma unroll
    for (int o = 16; o; o >>= 1) vs += __shfl_xor_sync(0xffffffffu, vs, o);
    __syncthreads();
    if ((t & 31) == 0) red[t >> 5] = vs;
    __syncthreads();
    tot = 0.f;
    #pragma unroll
    for (int i = 0; i < 8; i++) tot += red[i];
    const float rstd = rsqrtf(tot * (1.f / DMODEL) + LNEPS);

    #pragma unroll
    for (int u = 0; u < 4; u++) {
        int c = t + u * 256;
        out[base + c] = (x[u] - mu) * rstd * g[c] + bta[c];
    }
}

// ---------------- launch ----------------
extern "C" void kernel_launch(void* const* d_in, const int* in_sizes, int n_in,
                              void* d_out, int out_size) {
    const float* w    = (const float*)d_in[0];
    const float* r    = (const float*)d_in[1];
    const float* qkvw = (const float*)d_in[3];
    const float* rw   = (const float*)d_in[4];
    const float* ow   = (const float*)d_in[5];
    const float* rrb  = (const float*)d_in[6];
    const float* rwb  = (const float*)d_in[7];
    const float* lng  = (const float*)d_in[8];
    const float* lnb  = (const float*)d_in[9];
    float* out = (float*)d_out;

    __half *headsH, *rkH, *vecH, *gbd, *wh, *rh, *qkvT, *rwT, *owT;
    float *headsV, *bk, *brv, *proj;
    cudaGetSymbolAddress((void**)&headsH, g_headsH);
    cudaGetSymbolAddress((void**)&headsV, g_headsV);
    cudaGetSymbolAddress((void**)&rkH,    g_rkH);
    cudaGetSymbolAddress((void**)&bk,     g_biask);
    cudaGetSymbolAddress((void**)&brv,    g_biasr);
    cudaGetSymbolAddress((void**)&vecH,   g_vecH);
    cudaGetSymbolAddress((void**)&proj,   g_proj);
    cudaGetSymbolAddress((void**)&gbd,    g_bd);
    cudaGetSymbolAddress((void**)&wh,     g_wh);
    cudaGetSymbolAddress((void**)&rh,     g_rh);
    cudaGetSymbolAddress((void**)&qkvT,   g_qkvT);
    cudaGetSymbolAddress((void**)&rwT,    g_rwT);
    cudaGetSymbolAddress((void**)&owT,    g_owT);

    cudaFuncSetAttribute(attn2, cudaFuncAttributeMaxDynamicSharedMemorySize, ATTN2_BYTES);
    cudaFuncSetAttribute(gemm_f16, cudaFuncAttributeMaxDynamicSharedMemorySize, GEMMH_SMEM);
    cudaFuncSetAttribute(gemm_qkv_rk, cudaFuncAttributeMaxDynamicSharedMemorySize, GEMMH_SMEM);
    cudaFuncSetAttribute(gemm_bd, cudaFuncAttributeMaxDynamicSharedMemorySize, BDH_SMEM);

    // 0) conversions: w,r -> fp16; weights -> fp16 transposed [N][K]
    const int n4w = NROWS * DMODEL / 4, n4r = QL * DMODEL / 4;
    conv_wr<<<(n4w + n4r) / 256, 256>>>((const float4*)w, (__half2*)wh, n4w,
                                        (const float4*)r, (__half2*)rh, n4r);
    convT<<<dim3(HCOLS / 32, DMODEL / 32), dim3(32, 8)>>>(qkvw, qkvT, DMODEL, HCOLS);
    convT<<<dim3(DMODEL / 32, DMODEL / 32), dim3(32, 8)>>>(rw, rwT, DMODEL, DMODEL);
    convT<<<dim3(DMODEL / 32, DMODEL / 32), dim3(32, 8)>>>(ow, owT, DMODEL, DMODEL);

    // 1) fused fp16 GEMM: heads (q|k fp16, v f32) and rk (fp16)
    gemm_qkv_rk<<<dim3(24, 40), 256, GEMMH_SMEM>>>(wh, qkvT, headsH, headsV, rh, rwT, rkH);

    // 2) biases
    bias_k_kernel<<<(BS * NHEAD * QL * 32) / 256, 256>>>(headsH, rwb, bk);
    bias_r_kernel<<<(NHEAD * QL * 32) / 256, 256>>>(rkH, rrb, brv);

    // 3) BD band (fp16 in/out)
    gemm_bd<<<dim3(8, 8, 64), 256, BDH_SMEM>>>(headsH, rkH, brv, gbd);

    // 4) flash attention (fp16 QK, tf32 PV, fp16 vec out)
    attn2<<<dim3(BS * NHEAD, QL / 128), 256, ATTN2_BYTES>>>(headsH, headsV, bk, gbd, vecH);

    // 5) proj = vec @ o_w (fp16 GEMM, f32 out)
    gemm_f16<<<dim3(DMODEL / 128, NROWS / 128), 256, GEMMH_SMEM>>>(
        vecH, owT, proj, DMODEL, DMODEL);

    // 6) out = LN(w + proj)
    ln_kernel<<<NROWS, 256>>>(w, proj, lng, lnb, out);
}